// round 10
// baseline (speedup 1.0000x reference)
#include <cuda_runtime.h>
#include <cuda_fp16.h>
#include <cstdint>

// ---------------------------------------------------------------------------
// DCNv2 + GroupNorm16.  B=4, Cin=Cout=256, H=W=64, K=3, s=1, p=1, g=16.
// Fused tensor-core kernel: phase1 = offset conv (HMMA, im2col fp16 A, exact)
// with bilinear meta to smem; phase2 = deformable-sampled HMMA GEMM with
// fp16-gathered activations, A split hi/lo fp16 (2 terms), B single fp16.
// GN partial stats fused in epilogue. compute_103 baseline PTX only.
// ---------------------------------------------------------------------------

// ---- device-global scratch -------------------------------------------------
__device__ __half g_xH[4 * 4096 * 256];       // x transposed to NHWC, fp16
__device__ __half g_wF16[72 * 256 * 32];      // main weight fp16 [ci][o][k]
__device__ __half g_wOf[72 * 32 * 32];        // offset weight fp16 [ci][o32][k]
__device__ float  g_conv[4 * 256 * 4096];     // conv out (pre-GN)
__device__ float  g_psum[64 * 32];            // per-(bg,tile) partial sums
__device__ float  g_pssum[64 * 32];
__device__ float  g_mu[64];
__device__ float  g_rs[64];

// ---- PTX helpers ----------------------------------------------------------
__device__ __forceinline__ unsigned smem_u32(const void* p) {
    unsigned a;
    asm("{ .reg .u64 t; cvta.to.shared.u64 t, %1; cvt.u32.u64 %0, t; }"
        : "=r"(a) : "l"(p));
    return a;
}
#define CP16(s, g) asm volatile("cp.async.cg.shared.global [%0], [%1], 16;" :: "r"(s), "l"(g) : "memory")
#define CP_COMMIT() asm volatile("cp.async.commit_group;" ::: "memory")
#define CP_WAIT0()  asm volatile("cp.async.wait_group 0;" ::: "memory")

#define LDSM4(r, addr)                                                        \
    asm volatile("ldmatrix.sync.aligned.m8n8.x4.shared.b16 {%0,%1,%2,%3}, [%4];" \
                 : "=r"((r)[0]), "=r"((r)[1]), "=r"((r)[2]), "=r"((r)[3])     \
                 : "r"(addr))

#define MMA(ap, a, b0, b1)                                                    \
    asm volatile("mma.sync.aligned.m16n8k16.row.col.f32.f16.f16.f32 "         \
                 "{%0,%1,%2,%3}, {%4,%5,%6,%7}, {%8,%9}, {%0,%1,%2,%3};"      \
                 : "+f"((ap)[0]), "+f"((ap)[1]), "+f"((ap)[2]), "+f"((ap)[3]) \
                 : "r"((a)[0]), "r"((a)[1]), "r"((a)[2]), "r"((a)[3]),        \
                   "r"(b0), "r"(b1))

__device__ __forceinline__ unsigned pack_h2(float s0, float s1) {
    __half2 h = __floats2half2_rn(s0, s1);
    return *reinterpret_cast<unsigned*>(&h);
}
__device__ __forceinline__ void split_pair(float s0, float s1,
                                           unsigned& hp, unsigned& lp) {
    __half h0 = __float2half(s0), h1 = __float2half(s1);
    __half2 hh = __halves2half2(h0, h1);
    hp = *reinterpret_cast<unsigned*>(&hh);
    lp = pack_h2(s0 - __half2float(h0), s1 - __half2float(h1));
}

// ---------------------------------------------------------------------------
// x NCHW fp32 -> NHWC fp16
// ---------------------------------------------------------------------------
__global__ void k_xT(const float* __restrict__ x) {
    __shared__ float t[32][33];
    int bx = blockIdx.x;                    // 4096 = b(4) * cblk(8) * pxblk(128)
    int pxb = bx & 127, cb = (bx >> 7) & 7, b = bx >> 10;
    int tx = threadIdx.x & 31, ty = threadIdx.x >> 5;
#pragma unroll
    for (int i = 0; i < 4; i++) {
        int c = cb * 32 + ty + i * 8;
        t[ty + i * 8][tx] = x[(((size_t)(b * 256 + c)) << 12) + pxb * 32 + tx];
    }
    __syncthreads();
#pragma unroll
    for (int i = 0; i < 4; i++) {
        int px = pxb * 32 + ty + i * 8;
        g_xH[(((size_t)b << 12) + px) * 256 + cb * 32 + tx] =
            __float2half(t[tx][ty + i * 8]);
    }
}

// ---------------------------------------------------------------------------
// main weight [O][C][3][3] -> fp16 [ci][o][k32];  ci = tap*8+cb, c = cb*32+k
// ---------------------------------------------------------------------------
__global__ void k_prepW(const float* __restrict__ w) {
    int o = blockIdx.x;
    for (int idx = threadIdx.x; idx < 2304; idx += 256) {
        int ci = idx >> 5, k = idx & 31;
        int tap = ci >> 3, c = ((ci & 7) << 5) + k;
        g_wF16[(size_t)ci * 8192 + o * 32 + k] =
            __float2half(w[o * 2304 + c * 9 + tap]);
    }
}

// ---------------------------------------------------------------------------
// offset weight [27][C][3][3] -> fp16 [ci][o(32, >=27 zero)][k32]
// ---------------------------------------------------------------------------
__global__ void k_offW(const float* __restrict__ wof) {
    int ci = blockIdx.x;
    int tap = ci >> 3, cb = ci & 7;
    for (int i = threadIdx.x; i < 1024; i += 256) {
        int o = i >> 5, k = i & 31;
        int c = (cb << 5) + k;
        float v = (o < 27) ? wof[o * 2304 + c * 9 + tap] : 0.f;
        g_wOf[ci * 1024 + i] = __float2half(v);
    }
}

// ---------------------------------------------------------------------------
// Fused kernel. Grid 128 = (b, 32 px-tiles of 128). 512 threads.
// SMEM layout (dynamic, 118784 B):
//   SA[buf][term]: 128 rows x 80B = 10240 each  ->  [0, 40960)
//   SB[buf]:       256 rows x 80B = 20480 each  ->  [40960, 81920)
//   META_I: idx[9][128][4] int   -> [81920, 100352)
//   META_W: wgt[9][128][4] float -> [100352, 118784)
// ---------------------------------------------------------------------------
#define SA(buf, term) ((buf) * 20480 + (term) * 10240)
#define SB(buf)       (40960 + (buf) * 20480)
#define META_I        81920
#define META_W        100352
#define SMEM_TOTAL    118784

__global__ __launch_bounds__(512, 1) void k_mainTC(const float* __restrict__ bof,
                                                   const float* __restrict__ bias) {
    extern __shared__ char sm[];
    unsigned smb = smem_u32(sm);
    int tid = threadIdx.x, lane = tid & 31, wid = tid >> 5;
    int b = blockIdx.x >> 5;
    int tile = blockIdx.x & 31;
    int p0 = tile << 7;

    const __half* xh = g_xH + ((size_t)b << 20);
    int px = tid >> 2, oct = tid & 3;     // A staging role (both phases)
    unsigned aoff = (unsigned)((lane & 15) * 80 + (lane >> 4) * 16);
    unsigned boff = (unsigned)((lane & 7) * 80 + ((lane >> 3) & 1) * 16 +
                               (lane >> 4) * 640);
    unsigned ao = (unsigned)(px * 80 + oct * 16);

    // =======================================================================
    // Phase 1: offset conv HMMA (fp16 A exact, no split).
    // 16 warps = (wm1 0..7) x (wn1 0..1), warp tile 16x16.
    // =======================================================================
    {
        int wm1 = wid & 7, wn1 = wid >> 3;
        float acc1[2][4];
#pragma unroll
        for (int i = 0; i < 2; i++)
#pragma unroll
            for (int j = 0; j < 4; j++) acc1[i][j] = 0.f;

        int gp = p0 + px, h = gp >> 6, w = gp & 63;
        uint4 qA;
        auto loadA1 = [&](int ci) {
            int tap = ci >> 3, cb = ci & 7;
            int py = h + tap / 3 - 1, pxx = w + tap % 3 - 1;
            if (py >= 0 && py < 64 && pxx >= 0 && pxx < 64) {
                qA = *(const uint4*)(xh + (((size_t)(py * 64 + pxx)) << 8) +
                                     (cb << 5) + (oct << 3));
            } else {
                qA = make_uint4(0u, 0u, 0u, 0u);
            }
        };
        auto loadB1 = [&](int ci, int buf) {
            if (tid < 128) {
                int row = tid >> 2, q = tid & 3;
                CP16(smb + SB(buf) + row * 80 + q * 16,
                     g_wOf + ci * 1024 + row * 32 + q * 8);
            }
            CP_COMMIT();
        };

        loadA1(0);
        loadB1(0, 0);
#pragma unroll 1
        for (int ci = 0; ci < 72; ci++) {
            int buf = ci & 1;
            *(uint4*)(sm + SA(buf, 0) + ao) = qA;
            CP_WAIT0();
            __syncthreads();
            if (ci < 71) { loadA1(ci + 1); loadB1(ci + 1, buf ^ 1); }
            unsigned aB = smb + (unsigned)(buf * 20480 + wm1 * 1280) + aoff;
            unsigned bB = smb + (unsigned)SB(buf) + (unsigned)(wn1 * 1280) + boff;
#pragma unroll
            for (int ks = 0; ks < 2; ks++) {
                unsigned ah[4], bh[4];
                LDSM4(ah, aB + ks * 32);
                LDSM4(bh, bB + ks * 32);
                MMA(acc1[0], ah, bh[0], bh[1]);
                MMA(acc1[1], ah, bh[2], bh[3]);
            }
            __syncthreads();
        }
        // om scratch -> smem (128 x 32 f32)
        float* som = (float*)(sm + 40960);
        {
            int row = wm1 * 16 + (lane >> 2);
            int col = wn1 * 16 + (lane & 3) * 2;
#pragma unroll
            for (int nt = 0; nt < 2; nt++) {
                int c = col + nt * 8;
                som[row * 32 + c] = acc1[nt][0];
                som[row * 32 + c + 1] = acc1[nt][1];
                som[(row + 8) * 32 + c] = acc1[nt][2];
                som[(row + 8) * 32 + c + 1] = acc1[nt][3];
            }
        }
        __syncthreads();
        // bilinear meta -> smem META
        int* sIdx = (int*)(sm + META_I);
        float* sWgt = (float*)(sm + META_W);
        for (int idx = tid; idx < 1152; idx += 512) {
            int pr = idx / 9, k = idx - pr * 9;
            float ay = som[pr * 32 + k] + __ldg(bof + k);
            float ax = som[pr * 32 + k + 9] + __ldg(bof + k + 9);
            float am = som[pr * 32 + k + 18] + __ldg(bof + k + 18);
            float m = 1.f / (1.f + __expf(-am));
            int gp2 = p0 + pr, hh = gp2 >> 6, ww = gp2 & 63;
            float py = (float)(hh + k / 3 - 1) + ay;
            float pxx = (float)(ww + (k - (k / 3) * 3) - 1) + ax;
            float y0f = floorf(py), x0f = floorf(pxx);
            float wy1 = py - y0f, wx1 = pxx - x0f;
            int y0 = (int)y0f, x0 = (int)x0f;
            int mo = (k * 128 + pr) * 4;
#pragma unroll
            for (int j = 0; j < 4; j++) {
                int dy = j >> 1, dx = j & 1;
                int yy = y0 + dy, xx = x0 + dx;
                float wv = (dy ? wy1 : 1.f - wy1) * (dx ? wx1 : 1.f - wx1);
                bool valid = (yy >= 0) && (yy < 64) && (xx >= 0) && (xx < 64);
                int yc = min(max(yy, 0), 63), xc = min(max(xx, 0), 63);
                sIdx[mo + j] = yc * 64 + xc;
                sWgt[mo + j] = valid ? wv * m : 0.f;
            }
        }
        __syncthreads();
    }

    // =======================================================================
    // Phase 2: main deformable GEMM.  16 warps = (wm 0..3) x (wn 0..3), 32x64.
    // fp16 gathers (1 LDG.128 per corner), fp32 sampling, A split hi/lo.
    // =======================================================================
    int wm = wid & 3, wn = wid >> 2;
    float acc[64];
#pragma unroll
    for (int i = 0; i < 64; i++) acc[i] = 0.f;

    int4 mi;
    float4 mw;
    float sampA[8];
    const int* sIdx = (const int*)(sm + META_I);
    const float* sWgt = (const float*)(sm + META_W);

    auto meta = [&](int tap) {
        mi = *(const int4*)(sIdx + (tap * 128 + px) * 4);
        mw = *(const float4*)(sWgt + (tap * 128 + px) * 4);
    };
#define CORNER0(IDX, W) {                                                     \
        uint4 q = *(const uint4*)(base + ((size_t)(IDX) << 8));               \
        float2 f;                                                             \
        f = __half22float2(*(__half2*)&q.x); sampA[0] = (W) * f.x; sampA[1] = (W) * f.y; \
        f = __half22float2(*(__half2*)&q.y); sampA[2] = (W) * f.x; sampA[3] = (W) * f.y; \
        f = __half22float2(*(__half2*)&q.z); sampA[4] = (W) * f.x; sampA[5] = (W) * f.y; \
        f = __half22float2(*(__half2*)&q.w); sampA[6] = (W) * f.x; sampA[7] = (W) * f.y; \
    }
#define CORNERA(IDX, W) {                                                     \
        uint4 q = *(const uint4*)(base + ((size_t)(IDX) << 8));               \
        float2 f;                                                             \
        f = __half22float2(*(__half2*)&q.x);                                  \
        sampA[0] = fmaf((W), f.x, sampA[0]); sampA[1] = fmaf((W), f.y, sampA[1]); \
        f = __half22float2(*(__half2*)&q.y);                                  \
        sampA[2] = fmaf((W), f.x, sampA[2]); sampA[3] = fmaf((W), f.y, sampA[3]); \
        f = __half22float2(*(__half2*)&q.z);                                  \
        sampA[4] = fmaf((W), f.x, sampA[4]); sampA[5] = fmaf((W), f.y, sampA[5]); \
        f = __half22float2(*(__half2*)&q.w);                                  \
        sampA[6] = fmaf((W), f.x, sampA[6]); sampA[7] = fmaf((W), f.y, sampA[7]); \
    }
    auto gather = [&](int cn) {
        const __half* base = xh + ((cn & 7) << 5) + oct * 8;
        CORNER0(mi.x, mw.x);
        CORNERA(mi.y, mw.y);
        CORNERA(mi.z, mw.z);
        CORNERA(mi.w, mw.w);
    };
    auto loadB = [&](int ci, int buf) {
        if (tid < 256) {
            const __half* g = g_wF16 + (size_t)ci * 8192 + tid * 32;
            unsigned s = smb + SB(buf) + tid * 80;
            CP16(s, g); CP16(s + 16, g + 8);
            CP16(s + 32, g + 16); CP16(s + 48, g + 24);
        }
        CP_COMMIT();
    };

    meta(0);
    gather(0);
    loadB(0, 0);

#pragma unroll 1
    for (int ci = 0; ci < 72; ci++) {
        int buf = ci & 1;
        {
            unsigned hp[4], lp[4];
            split_pair(sampA[0], sampA[1], hp[0], lp[0]);
            split_pair(sampA[2], sampA[3], hp[1], lp[1]);
            split_pair(sampA[4], sampA[5], hp[2], lp[2]);
            split_pair(sampA[6], sampA[7], hp[3], lp[3]);
            *(uint4*)(sm + SA(buf, 0) + ao) = make_uint4(hp[0], hp[1], hp[2], hp[3]);
            *(uint4*)(sm + SA(buf, 1) + ao) = make_uint4(lp[0], lp[1], lp[2], lp[3]);
        }
        CP_WAIT0();
        __syncthreads();

        if (ci < 71) {
            int cn = ci + 1;
            if ((cn & 7) == 0) meta(cn >> 3);
            gather(cn);
            loadB(cn, buf ^ 1);
        }

#pragma unroll
        for (int ks = 0; ks < 2; ks++) {
            unsigned ab = smb + (unsigned)(buf * 20480 + wm * 2560 + ks * 32) + aoff;
            unsigned ah0[4], ah1[4], al0[4], al1[4];
            LDSM4(ah0, ab);
            LDSM4(ah1, ab + 1280);
            LDSM4(al0, ab + 10240);
            LDSM4(al1, ab + 11520);
            unsigned bb = smb + (unsigned)(SB(buf) + wn * 5120 + ks * 32) + boff;
#pragma unroll
            for (int ntp = 0; ntp < 4; ntp++) {
                unsigned bh[4];
                LDSM4(bh, bb + ntp * 1280);
                float* a00 = &acc[(ntp * 2) * 4];
                float* a01 = &acc[(ntp * 2 + 1) * 4];
                float* a10 = &acc[(8 + ntp * 2) * 4];
                float* a11 = &acc[(8 + ntp * 2 + 1) * 4];
                MMA(a00, ah0, bh[0], bh[1]);
                MMA(a01, ah0, bh[2], bh[3]);
                MMA(a10, ah1, bh[0], bh[1]);
                MMA(a11, ah1, bh[2], bh[3]);
                MMA(a00, al0, bh[0], bh[1]);
                MMA(a01, al0, bh[2], bh[3]);
                MMA(a10, al1, bh[0], bh[1]);
                MMA(a11, al1, bh[2], bh[3]);
            }
        }
        __syncthreads();
    }

    // ---- epilogue: bias add, store, fused GN partial stats ----
    float pg[4] = {0.f, 0.f, 0.f, 0.f};
    float pq[4] = {0.f, 0.f, 0.f, 0.f};
    int pxb = p0 + wm * 32 + (lane >> 2);
#pragma unroll
    for (int mt = 0; mt < 2; mt++) {
#pragma unroll
        for (int nt = 0; nt < 8; nt++) {
            float* ap = &acc[(mt * 8 + nt) * 4];
            int o = wn * 64 + nt * 8 + (lane & 3) * 2;
            float bv0 = __ldg(bias + o), bv1 = __ldg(bias + o + 1);
            int pxm = pxb + mt * 16;
            size_t r0 = (((size_t)(b * 256 + o)) << 12) + pxm;
            size_t r1 = r0 + 4096;
            float v0 = ap[0] + bv0, v1 = ap[1] + bv1;
            float v2 = ap[2] + bv0, v3 = ap[3] + bv1;
            g_conv[r0] = v0;
            g_conv[r1] = v1;
            g_conv[r0 + 8] = v2;
            g_conv[r1 + 8] = v3;
            int j = nt >> 1;
            pg[j] += v0 + v1 + v2 + v3;
            pq[j] += v0 * v0 + v1 * v1 + v2 * v2 + v3 * v3;
        }
    }
#pragma unroll
    for (int j = 0; j < 4; j++) {
#pragma unroll
        for (int s = 16; s > 0; s >>= 1) {
            pg[j] += __shfl_down_sync(0xFFFFFFFFu, pg[j], s);
            pq[j] += __shfl_down_sync(0xFFFFFFFFu, pq[j], s);
        }
    }
    float* red = (float*)sm;   // 16 warps x 8 floats
    if (lane == 0) {
#pragma unroll
        for (int j = 0; j < 4; j++) {
            red[wid * 8 + j] = pg[j];
            red[wid * 8 + 4 + j] = pq[j];
        }
    }
    __syncthreads();
    if (tid < 32) {
        int group = tid >> 1, which = tid & 1;
        int wnb = group >> 2;
        float v = 0.f;
#pragma unroll
        for (int wmi = 0; wmi < 4; wmi++)
            v += red[(wnb * 4 + wmi) * 8 + (group & 3) + 4 * which];
        if (which == 0) g_psum[(b * 16 + group) * 32 + tile] = v;
        else            g_pssum[(b * 16 + group) * 32 + tile] = v;
    }
}

// ---------------------------------------------------------------------------
// GN stats finalize: 64 blocks x 32 threads
// ---------------------------------------------------------------------------
__global__ void k_statsF() {
    int bg = blockIdx.x, t = threadIdx.x;
    float s = g_psum[bg * 32 + t];
    float q = g_pssum[bg * 32 + t];
#pragma unroll
    for (int o = 16; o > 0; o >>= 1) {
        s += __shfl_down_sync(0xFFFFFFFFu, s, o);
        q += __shfl_down_sync(0xFFFFFFFFu, q, o);
    }
    if (t == 0) {
        float mu = s * (1.f / 65536.f);
        float var = q * (1.f / 65536.f) - mu * mu;
        g_mu[bg] = mu;
        g_rs[bg] = rsqrtf(var + 1e-5f);
    }
}

// ---------------------------------------------------------------------------
// Normalize + affine -> d_out.  2048 blocks x 256 thr x 2 float4.
// ---------------------------------------------------------------------------
__global__ void k_norm(const float* __restrict__ gamma,
                       const float* __restrict__ beta,
                       float* __restrict__ out) {
    int i = blockIdx.x * 512 + threadIdx.x;
#pragma unroll
    for (int t = 0; t < 2; t++, i += 256) {
        float4 v = ((const float4*)g_conv)[i];
        int bc = i >> 10;
        int c = bc & 255, b = bc >> 8;
        int bg = b * 16 + (c >> 4);
        float sc = g_rs[bg] * gamma[c];
        float sh = beta[c] - g_mu[bg] * sc;
        v.x = v.x * sc + sh;
        v.y = v.y * sc + sh;
        v.z = v.z * sc + sh;
        v.w = v.w * sc + sh;
        ((float4*)out)[i] = v;
    }
}

// ---------------------------------------------------------------------------
extern "C" void kernel_launch(void* const* d_in, const int* in_sizes, int n_in,
                              void* d_out, int out_size) {
    const float* x = nullptr;
    const float* w_off = nullptr;
    const float* b_off = nullptr;
    const float* weight = nullptr;
    const float* v256[3] = {nullptr, nullptr, nullptr};
    int n256 = 0;
    for (int i = 0; i < n_in; i++) {
        int s = in_sizes[i];
        const float* ptr = (const float*)d_in[i];
        if (s == 4194304) x = ptr;
        else if (s == 62208) w_off = ptr;
        else if (s == 27) b_off = ptr;
        else if (s == 589824) weight = ptr;
        else if (s == 256 && n256 < 3) v256[n256++] = ptr;
    }
    const float* bias  = v256[0];
    const float* gamma = v256[1];
    const float* beta  = v256[2];
    float* out = (float*)d_out;

    cudaFuncSetAttribute(k_mainTC, cudaFuncAttributeMaxDynamicSharedMemorySize,
                         SMEM_TOTAL);

    k_xT<<<4096, 256>>>(x);
    k_prepW<<<256, 256>>>(weight);
    k_offW<<<72, 256>>>(w_off);
    k_mainTC<<<128, 512, SMEM_TOTAL>>>(b_off, bias);
    k_statsF<<<64, 32>>>();
    k_norm<<<2048, 256>>>(gamma, beta, out);
}

// round 11
// speedup vs baseline: 1.3525x; 1.3525x over previous
#include <cuda_runtime.h>
#include <cuda_fp16.h>
#include <cstdint>

// ---------------------------------------------------------------------------
// DCNv2 + GroupNorm16.  B=4, Cin=Cout=256, H=W=64, K=3, s=1, p=1, g=16.
// Fused tensor-core kernel, M=64 px tiles, 2 CTAs/SM for phase overlap.
// phase1 = offset conv HMMA (fp16 im2col A, single term) + bilinear meta;
// phase2 = deformable-sampled HMMA GEMM (fp32 gathers, A split hi/lo fp16,
// B single fp16). GN partial stats fused. compute_103 baseline PTX only.
// ---------------------------------------------------------------------------

// ---- device-global scratch -------------------------------------------------
__device__ float  g_xT[4 * 4096 * 256];       // x NHWC fp32 (phase2 gathers)
__device__ __half g_xH[4 * 4096 * 256];       // x NHWC fp16 (phase1 im2col)
__device__ __half g_wF16[72 * 256 * 32];      // main weight fp16 [ci][o][k]
__device__ __half g_wOf[72 * 32 * 32];        // offset weight fp16 [ci][o32][k]
__device__ float  g_conv[4 * 256 * 4096];     // conv out (pre-GN)
__device__ float  g_psum[64 * 64];            // per-(bg,tile) partial sums
__device__ float  g_pssum[64 * 64];
__device__ float  g_mu[64];
__device__ float  g_rs[64];

// ---- PTX helpers ----------------------------------------------------------
__device__ __forceinline__ unsigned smem_u32(const void* p) {
    unsigned a;
    asm("{ .reg .u64 t; cvta.to.shared.u64 t, %1; cvt.u32.u64 %0, t; }"
        : "=r"(a) : "l"(p));
    return a;
}
#define CP16(s, g) asm volatile("cp.async.cg.shared.global [%0], [%1], 16;" :: "r"(s), "l"(g) : "memory")
#define CP_COMMIT() asm volatile("cp.async.commit_group;" ::: "memory")
#define CP_WAIT0()  asm volatile("cp.async.wait_group 0;" ::: "memory")

#define LDSM4(r, addr)                                                        \
    asm volatile("ldmatrix.sync.aligned.m8n8.x4.shared.b16 {%0,%1,%2,%3}, [%4];" \
                 : "=r"((r)[0]), "=r"((r)[1]), "=r"((r)[2]), "=r"((r)[3])     \
                 : "r"(addr))

#define MMA(ap, a, b0, b1)                                                    \
    asm volatile("mma.sync.aligned.m16n8k16.row.col.f32.f16.f16.f32 "         \
                 "{%0,%1,%2,%3}, {%4,%5,%6,%7}, {%8,%9}, {%0,%1,%2,%3};"      \
                 : "+f"((ap)[0]), "+f"((ap)[1]), "+f"((ap)[2]), "+f"((ap)[3]) \
                 : "r"((a)[0]), "r"((a)[1]), "r"((a)[2]), "r"((a)[3]),        \
                   "r"(b0), "r"(b1))

__device__ __forceinline__ unsigned pack_h2(float s0, float s1) {
    __half2 h = __floats2half2_rn(s0, s1);
    return *reinterpret_cast<unsigned*>(&h);
}
__device__ __forceinline__ void split_pair(float s0, float s1,
                                           unsigned& hp, unsigned& lp) {
    __half h0 = __float2half(s0), h1 = __float2half(s1);
    __half2 hh = __halves2half2(h0, h1);
    hp = *reinterpret_cast<unsigned*>(&hh);
    lp = pack_h2(s0 - __half2float(h0), s1 - __half2float(h1));
}

// ---------------------------------------------------------------------------
// x NCHW fp32 -> NHWC fp32 + fp16
// ---------------------------------------------------------------------------
__global__ void k_xT(const float* __restrict__ x) {
    __shared__ float t[32][33];
    int bx = blockIdx.x;                    // 4096 = b(4) * cblk(8) * pxblk(128)
    int pxb = bx & 127, cb = (bx >> 7) & 7, b = bx >> 10;
    int tx = threadIdx.x & 31, ty = threadIdx.x >> 5;
#pragma unroll
    for (int i = 0; i < 4; i++) {
        int c = cb * 32 + ty + i * 8;
        t[ty + i * 8][tx] = x[(((size_t)(b * 256 + c)) << 12) + pxb * 32 + tx];
    }
    __syncthreads();
#pragma unroll
    for (int i = 0; i < 4; i++) {
        int px = pxb * 32 + ty + i * 8;
        float v = t[tx][ty + i * 8];
        size_t dst = (((size_t)b << 12) + px) * 256 + cb * 32 + tx;
        g_xT[dst] = v;
        g_xH[dst] = __float2half(v);
    }
}

// ---------------------------------------------------------------------------
// main weight [O][C][3][3] -> fp16 [ci][o][k32];  ci = tap*8+cb, c = cb*32+k
// ---------------------------------------------------------------------------
__global__ void k_prepW(const float* __restrict__ w) {
    int o = blockIdx.x;
    for (int idx = threadIdx.x; idx < 2304; idx += 256) {
        int ci = idx >> 5, k = idx & 31;
        int tap = ci >> 3, c = ((ci & 7) << 5) + k;
        g_wF16[(size_t)ci * 8192 + o * 32 + k] =
            __float2half(w[o * 2304 + c * 9 + tap]);
    }
}

// ---------------------------------------------------------------------------
// offset weight [27][C][3][3] -> fp16 [ci][o(32, >=27 zero)][k32]
// ---------------------------------------------------------------------------
__global__ void k_offW(const float* __restrict__ wof) {
    int ci = blockIdx.x;
    int tap = ci >> 3, cb = ci & 7;
    for (int i = threadIdx.x; i < 1024; i += 256) {
        int o = i >> 5, k = i & 31;
        int c = (cb << 5) + k;
        float v = (o < 27) ? wof[o * 2304 + c * 9 + tap] : 0.f;
        g_wOf[ci * 1024 + i] = __float2half(v);
    }
}

// ---------------------------------------------------------------------------
// Fused kernel. Grid 256 = (b, 64 px-tiles of 64). 256 threads, 2 CTAs/SM.
// SMEM (dynamic, 79872 B):
//   SA[buf][term]: 64 rows x 80B = 5120 each  -> [0, 20480)
//   SB[buf]:       256 rows x 80B = 20480 each -> [20480, 61440)
//     (phase1 uses first 2560 of each buf; om scratch 64x32 f32 at 20480)
//   META_I: idx[9][64][4] int   -> [61440, 70656)
//   META_W: wgt[9][64][4] float -> [70656, 79872)
// ---------------------------------------------------------------------------
#define SA(buf, term) ((buf) * 10240 + (term) * 5120)
#define SB(buf)       (20480 + (buf) * 20480)
#define META_I        61440
#define META_W        70656
#define SMEM_TOTAL    79872

__global__ __launch_bounds__(256, 2) void k_mainTC(const float* __restrict__ bof,
                                                   const float* __restrict__ bias) {
    extern __shared__ char sm[];
    unsigned smb = smem_u32(sm);
    int tid = threadIdx.x, lane = tid & 31, wid = tid >> 5;
    int b = blockIdx.x >> 6;
    int tile = blockIdx.x & 63;
    int p0 = tile << 6;

    int px = tid >> 2, oct = tid & 3;     // A staging role (both phases)
    unsigned aoff = (unsigned)((lane & 15) * 80 + (lane >> 4) * 16);
    unsigned boff = (unsigned)((lane & 7) * 80 + ((lane >> 3) & 1) * 16 +
                               (lane >> 4) * 640);
    unsigned ao = (unsigned)(px * 80 + oct * 16);

    // =======================================================================
    // Phase 1: offset conv HMMA (fp16 im2col A, single term).
    // 8 warps = (wm1 0..3) x (wn1 0..1), warp tile 16x16.
    // =======================================================================
    {
        int wm1 = wid & 3, wn1 = wid >> 2;
        float acc1[2][4];
#pragma unroll
        for (int i = 0; i < 2; i++)
#pragma unroll
            for (int j = 0; j < 4; j++) acc1[i][j] = 0.f;

        const __half* xh = g_xH + ((size_t)b << 20);
        int gp = p0 + px, h = gp >> 6, w = gp & 63;
        uint4 qA;
        auto loadA1 = [&](int ci) {
            int tap = ci >> 3, cb = ci & 7;
            int py = h + tap / 3 - 1, pxx = w + tap % 3 - 1;
            if (py >= 0 && py < 64 && pxx >= 0 && pxx < 64) {
                qA = *(const uint4*)(xh + (((size_t)(py * 64 + pxx)) << 8) +
                                     (cb << 5) + (oct << 3));
            } else {
                qA = make_uint4(0u, 0u, 0u, 0u);
            }
        };
        auto loadB1 = [&](int ci, int buf) {
            if (tid < 128) {
                int row = tid >> 2, q = tid & 3;
                CP16(smb + SB(buf) + row * 80 + q * 16,
                     g_wOf + ci * 1024 + row * 32 + q * 8);
            }
            CP_COMMIT();
        };

        loadA1(0);
        loadB1(0, 0);
#pragma unroll 1
        for (int ci = 0; ci < 72; ci++) {
            int buf = ci & 1;
            *(uint4*)(sm + SA(buf, 0) + ao) = qA;
            CP_WAIT0();
            __syncthreads();
            if (ci < 71) { loadA1(ci + 1); loadB1(ci + 1, buf ^ 1); }
            unsigned aB = smb + (unsigned)(buf * 10240 + wm1 * 1280) + aoff;
            unsigned bB = smb + (unsigned)SB(buf) + (unsigned)(wn1 * 1280) + boff;
#pragma unroll
            for (int ks = 0; ks < 2; ks++) {
                unsigned ah[4], bh[4];
                LDSM4(ah, aB + ks * 32);
                LDSM4(bh, bB + ks * 32);
                MMA(acc1[0], ah, bh[0], bh[1]);
                MMA(acc1[1], ah, bh[2], bh[3]);
            }
            __syncthreads();
        }
        // om scratch (64 x 32 f32) at sm+20480
        float* som = (float*)(sm + 20480);
        {
            int row = wm1 * 16 + (lane >> 2);
            int col = wn1 * 16 + (lane & 3) * 2;
#pragma unroll
            for (int nt = 0; nt < 2; nt++) {
                int c = col + nt * 8;
                som[row * 32 + c] = acc1[nt][0];
                som[row * 32 + c + 1] = acc1[nt][1];
                som[(row + 8) * 32 + c] = acc1[nt][2];
                som[(row + 8) * 32 + c + 1] = acc1[nt][3];
            }
        }
        __syncthreads();
        // bilinear meta -> smem META
        int* sIdx = (int*)(sm + META_I);
        float* sWgt = (float*)(sm + META_W);
        for (int idx = tid; idx < 576; idx += 256) {
            int pr = idx / 9, k = idx - pr * 9;
            float ay = som[pr * 32 + k] + __ldg(bof + k);
            float ax = som[pr * 32 + k + 9] + __ldg(bof + k + 9);
            float am = som[pr * 32 + k + 18] + __ldg(bof + k + 18);
            float m = 1.f / (1.f + __expf(-am));
            int gp2 = p0 + pr, hh = gp2 >> 6, ww = gp2 & 63;
            float py = (float)(hh + k / 3 - 1) + ay;
            float pxx = (float)(ww + (k - (k / 3) * 3) - 1) + ax;
            float y0f = floorf(py), x0f = floorf(pxx);
            float wy1 = py - y0f, wx1 = pxx - x0f;
            int y0 = (int)y0f, x0 = (int)x0f;
            int mo = (k * 64 + pr) * 4;
#pragma unroll
            for (int j = 0; j < 4; j++) {
                int dy = j >> 1, dx = j & 1;
                int yy = y0 + dy, xx = x0 + dx;
                float wv = (dy ? wy1 : 1.f - wy1) * (dx ? wx1 : 1.f - wx1);
                bool valid = (yy >= 0) && (yy < 64) && (xx >= 0) && (xx < 64);
                int yc = min(max(yy, 0), 63), xc = min(max(xx, 0), 63);
                sIdx[mo + j] = yc * 64 + xc;
                sWgt[mo + j] = valid ? wv * m : 0.f;
            }
        }
        __syncthreads();
    }

    // =======================================================================
    // Phase 2: main deformable GEMM. 8 warps = (wm 0..1) x (wn 0..3), 32x64.
    // fp32 gathers, fp32 sampling, A split hi/lo fp16, B single fp16.
    // =======================================================================
    int wm = wid & 1, wn = wid >> 1;
    float acc[64];
#pragma unroll
    for (int i = 0; i < 64; i++) acc[i] = 0.f;

    const float* xb = g_xT + ((size_t)b << 20);
    int4 mi;
    float4 mw;
    float sampA[8];
    const int* sIdx = (const int*)(sm + META_I);
    const float* sWgt = (const float*)(sm + META_W);

    auto meta = [&](int tap) {
        mi = *(const int4*)(sIdx + (tap * 64 + px) * 4);
        mw = *(const float4*)(sWgt + (tap * 64 + px) * 4);
    };
    auto gather = [&](int cn) {
        const float* base = xb + ((cn & 7) << 5) + oct * 8;
        const float* pp = base + ((size_t)mi.x << 8);
        float4 u0 = *(const float4*)pp, u1 = *(const float4*)(pp + 4);
        sampA[0] = mw.x * u0.x; sampA[1] = mw.x * u0.y;
        sampA[2] = mw.x * u0.z; sampA[3] = mw.x * u0.w;
        sampA[4] = mw.x * u1.x; sampA[5] = mw.x * u1.y;
        sampA[6] = mw.x * u1.z; sampA[7] = mw.x * u1.w;
        pp = base + ((size_t)mi.y << 8);
        u0 = *(const float4*)pp; u1 = *(const float4*)(pp + 4);
        sampA[0] = fmaf(mw.y, u0.x, sampA[0]); sampA[1] = fmaf(mw.y, u0.y, sampA[1]);
        sampA[2] = fmaf(mw.y, u0.z, sampA[2]); sampA[3] = fmaf(mw.y, u0.w, sampA[3]);
        sampA[4] = fmaf(mw.y, u1.x, sampA[4]); sampA[5] = fmaf(mw.y, u1.y, sampA[5]);
        sampA[6] = fmaf(mw.y, u1.z, sampA[6]); sampA[7] = fmaf(mw.y, u1.w, sampA[7]);
        pp = base + ((size_t)mi.z << 8);
        u0 = *(const float4*)pp; u1 = *(const float4*)(pp + 4);
        sampA[0] = fmaf(mw.z, u0.x, sampA[0]); sampA[1] = fmaf(mw.z, u0.y, sampA[1]);
        sampA[2] = fmaf(mw.z, u0.z, sampA[2]); sampA[3] = fmaf(mw.z, u0.w, sampA[3]);
        sampA[4] = fmaf(mw.z, u1.x, sampA[4]); sampA[5] = fmaf(mw.z, u1.y, sampA[5]);
        sampA[6] = fmaf(mw.z, u1.z, sampA[6]); sampA[7] = fmaf(mw.z, u1.w, sampA[7]);
        pp = base + ((size_t)mi.w << 8);
        u0 = *(const float4*)pp; u1 = *(const float4*)(pp + 4);
        sampA[0] = fmaf(mw.w, u0.x, sampA[0]); sampA[1] = fmaf(mw.w, u0.y, sampA[1]);
        sampA[2] = fmaf(mw.w, u0.z, sampA[2]); sampA[3] = fmaf(mw.w, u0.w, sampA[3]);
        sampA[4] = fmaf(mw.w, u1.x, sampA[4]); sampA[5] = fmaf(mw.w, u1.y, sampA[5]);
        sampA[6] = fmaf(mw.w, u1.z, sampA[6]); sampA[7] = fmaf(mw.w, u1.w, sampA[7]);
    };
    auto loadB = [&](int ci, int buf) {
        const __half* g = g_wF16 + (size_t)ci * 8192 + tid * 32;
        unsigned s = smb + SB(buf) + tid * 80;
        CP16(s, g); CP16(s + 16, g + 8);
        CP16(s + 32, g + 16); CP16(s + 48, g + 24);
        CP_COMMIT();
    };

    meta(0);
    gather(0);
    loadB(0, 0);

#pragma unroll 1
    for (int ci = 0; ci < 72; ci++) {
        int buf = ci & 1;
        {
            unsigned hp[4], lp[4];
            split_pair(sampA[0], sampA[1], hp[0], lp[0]);
            split_pair(sampA[2], sampA[3], hp[1], lp[1]);
            split_pair(sampA[4], sampA[5], hp[2], lp[2]);
            split_pair(sampA[6], sampA[7], hp[3], lp[3]);
            *(uint4*)(sm + SA(buf, 0) + ao) = make_uint4(hp[0], hp[1], hp[2], hp[3]);
            *(uint4*)(sm + SA(buf, 1) + ao) = make_uint4(lp[0], lp[1], lp[2], lp[3]);
        }
        CP_WAIT0();
        __syncthreads();

        if (ci < 71) {
            int cn = ci + 1;
            if ((cn & 7) == 0) meta(cn >> 3);
            gather(cn);
            loadB(cn, buf ^ 1);
        }

#pragma unroll
        for (int ks = 0; ks < 2; ks++) {
            unsigned ab = smb + (unsigned)(buf * 10240 + wm * 2560 + ks * 32) + aoff;
            unsigned ah0[4], ah1[4], al0[4], al1[4];
            LDSM4(ah0, ab);
            LDSM4(ah1, ab + 1280);
            LDSM4(al0, ab + 5120);
            LDSM4(al1, ab + 6400);
            unsigned bb = smb + (unsigned)(SB(buf) + wn * 5120 + ks * 32) + boff;
#pragma unroll
            for (int ntp = 0; ntp < 4; ntp++) {
                unsigned bh[4];
                LDSM4(bh, bb + ntp * 1280);
                float* a00 = &acc[(ntp * 2) * 4];
                float* a01 = &acc[(ntp * 2 + 1) * 4];
                float* a10 = &acc[(8 + ntp * 2) * 4];
                float* a11 = &acc[(8 + ntp * 2 + 1) * 4];
                MMA(a00, ah0, bh[0], bh[1]);
                MMA(a01, ah0, bh[2], bh[3]);
                MMA(a10, ah1, bh[0], bh[1]);
                MMA(a11, ah1, bh[2], bh[3]);
                MMA(a00, al0, bh[0], bh[1]);
                MMA(a01, al0, bh[2], bh[3]);
                MMA(a10, al1, bh[0], bh[1]);
                MMA(a11, al1, bh[2], bh[3]);
            }
        }
        __syncthreads();
    }

    // ---- epilogue: bias add, store, fused GN partial stats ----
    float pg[4] = {0.f, 0.f, 0.f, 0.f};
    float pq[4] = {0.f, 0.f, 0.f, 0.f};
    int pxb = p0 + wm * 32 + (lane >> 2);
#pragma unroll
    for (int mt = 0; mt < 2; mt++) {
#pragma unroll
        for (int nt = 0; nt < 8; nt++) {
            float* ap = &acc[(mt * 8 + nt) * 4];
            int o = wn * 64 + nt * 8 + (lane & 3) * 2;
            float bv0 = __ldg(bias + o), bv1 = __ldg(bias + o + 1);
            int pxm = pxb + mt * 16;
            size_t r0 = (((size_t)(b * 256 + o)) << 12) + pxm;
            size_t r1 = r0 + 4096;
            float v0 = ap[0] + bv0, v1 = ap[1] + bv1;
            float v2 = ap[2] + bv0, v3 = ap[3] + bv1;
            g_conv[r0] = v0;
            g_conv[r1] = v1;
            g_conv[r0 + 8] = v2;
            g_conv[r1 + 8] = v3;
            int j = nt >> 1;
            pg[j] += v0 + v1 + v2 + v3;
            pq[j] += v0 * v0 + v1 * v1 + v2 * v2 + v3 * v3;
        }
    }
#pragma unroll
    for (int j = 0; j < 4; j++) {
#pragma unroll
        for (int s = 16; s > 0; s >>= 1) {
            pg[j] += __shfl_down_sync(0xFFFFFFFFu, pg[j], s);
            pq[j] += __shfl_down_sync(0xFFFFFFFFu, pq[j], s);
        }
    }
    float* red = (float*)sm;   // 8 warps x 8 floats
    if (lane == 0) {
#pragma unroll
        for (int j = 0; j < 4; j++) {
            red[wid * 8 + j] = pg[j];
            red[wid * 8 + 4 + j] = pq[j];
        }
    }
    __syncthreads();
    if (tid < 32) {
        int group = tid >> 1, which = tid & 1;   // 16 groups x {sum,ssum}
        int wnb = group >> 2;
        float v = 0.f;
#pragma unroll
        for (int wmi = 0; wmi < 2; wmi++)
            v += red[(wnb * 2 + wmi) * 8 + (group & 3) + 4 * which];
        if (which == 0) g_psum[(b * 16 + group) * 64 + tile] = v;
        else            g_pssum[(b * 16 + group) * 64 + tile] = v;
    }
}

// ---------------------------------------------------------------------------
// GN stats finalize: 64 blocks x 32 threads (each sums 2 of 64 tiles)
// ---------------------------------------------------------------------------
__global__ void k_statsF() {
    int bg = blockIdx.x, t = threadIdx.x;
    float s = g_psum[bg * 64 + t] + g_psum[bg * 64 + t + 32];
    float q = g_pssum[bg * 64 + t] + g_pssum[bg * 64 + t + 32];
#pragma unroll
    for (int o = 16; o > 0; o >>= 1) {
        s += __shfl_down_sync(0xFFFFFFFFu, s, o);
        q += __shfl_down_sync(0xFFFFFFFFu, q, o);
    }
    if (t == 0) {
        float mu = s * (1.f / 65536.f);
        float var = q * (1.f / 65536.f) - mu * mu;
        g_mu[bg] = mu;
        g_rs[bg] = rsqrtf(var + 1e-5f);
    }
}

// ---------------------------------------------------------------------------
// Normalize + affine -> d_out.  2048 blocks x 256 thr x 2 float4.
// ---------------------------------------------------------------------------
__global__ void k_norm(const float* __restrict__ gamma,
                       const float* __restrict__ beta,
                       float* __restrict__ out) {
    int i = blockIdx.x * 512 + threadIdx.x;
#pragma unroll
    for (int t = 0; t < 2; t++, i += 256) {
        float4 v = ((const float4*)g_conv)[i];
        int bc = i >> 10;
        int c = bc & 255, b = bc >> 8;
        int bg = b * 16 + (c >> 4);
        float sc = g_rs[bg] * gamma[c];
        float sh = beta[c] - g_mu[bg] * sc;
        v.x = v.x * sc + sh;
        v.y = v.y * sc + sh;
        v.z = v.z * sc + sh;
        v.w = v.w * sc + sh;
        ((float4*)out)[i] = v;
    }
}

// ---------------------------------------------------------------------------
extern "C" void kernel_launch(void* const* d_in, const int* in_sizes, int n_in,
                              void* d_out, int out_size) {
    const float* x = nullptr;
    const float* w_off = nullptr;
    const float* b_off = nullptr;
    const float* weight = nullptr;
    const float* v256[3] = {nullptr, nullptr, nullptr};
    int n256 = 0;
    for (int i = 0; i < n_in; i++) {
        int s = in_sizes[i];
        const float* ptr = (const float*)d_in[i];
        if (s == 4194304) x = ptr;
        else if (s == 62208) w_off = ptr;
        else if (s == 27) b_off = ptr;
        else if (s == 589824) weight = ptr;
        else if (s == 256 && n256 < 3) v256[n256++] = ptr;
    }
    const float* bias  = v256[0];
    const float* gamma = v256[1];
    const float* beta  = v256[2];
    float* out = (float*)d_out;

    cudaFuncSetAttribute(k_mainTC, cudaFuncAttributeMaxDynamicSharedMemorySize,
                         SMEM_TOTAL);

    k_xT<<<4096, 256>>>(x);
    k_prepW<<<256, 256>>>(weight);
    k_offW<<<72, 256>>>(w_off);
    k_mainTC<<<256, 256, SMEM_TOTAL>>>(b_off, bias);
    k_statsF<<<64, 32>>>();
    k_norm<<<2048, 256>>>(gamma, beta, out);
}

// round 12
// speedup vs baseline: 1.5844x; 1.1715x over previous
#include <cuda_runtime.h>
#include <cuda_fp16.h>
#include <cstdint>

// ---------------------------------------------------------------------------
// DCNv2 + GroupNorm16.  B=4, Cin=Cout=256, H=W=64, K=3, s=1, p=1, g=16.
// Fused tensor-core kernel (M=128 tiles, 512 thr, grid 128):
//  phase1 = offset conv HMMA (fp16 im2col A, single term) + bilinear meta;
//  phase2 = deformable-sampled HMMA GEMM (fp32 gathers with software
//  load/use splitting so LDG latency hides under MMA; A split hi/lo fp16,
//  B single fp16). One barrier per chunk. GN partial stats fused.
// compute_103 baseline PTX only.
// ---------------------------------------------------------------------------

// ---- device-global scratch -------------------------------------------------
__device__ float  g_xT[4 * 4096 * 256];       // x NHWC fp32 (phase2 gathers)
__device__ __half g_xH[4 * 4096 * 256];       // x NHWC fp16 (phase1 im2col)
__device__ __half g_wF16[72 * 256 * 32];      // main weight fp16 [ci][o][k]
__device__ __half g_wOf[72 * 32 * 32];        // offset weight fp16 [ci][o32][k]
__device__ float  g_conv[4 * 256 * 4096];     // conv out (pre-GN)
__device__ float  g_psum[64 * 32];            // per-(bg,tile) partial sums
__device__ float  g_pssum[64 * 32];
__device__ float  g_mu[64];
__device__ float  g_rs[64];

// ---- PTX helpers ----------------------------------------------------------
__device__ __forceinline__ unsigned smem_u32(const void* p) {
    unsigned a;
    asm("{ .reg .u64 t; cvta.to.shared.u64 t, %1; cvt.u32.u64 %0, t; }"
        : "=r"(a) : "l"(p));
    return a;
}
#define CP16(s, g) asm volatile("cp.async.cg.shared.global [%0], [%1], 16;" :: "r"(s), "l"(g) : "memory")
#define CP_COMMIT() asm volatile("cp.async.commit_group;" ::: "memory")
#define CP_WAIT0()  asm volatile("cp.async.wait_group 0;" ::: "memory")

#define LDSM4(r, addr)                                                        \
    asm volatile("ldmatrix.sync.aligned.m8n8.x4.shared.b16 {%0,%1,%2,%3}, [%4];" \
                 : "=r"((r)[0]), "=r"((r)[1]), "=r"((r)[2]), "=r"((r)[3])     \
                 : "r"(addr))

#define MMA(ap, a, b0, b1)                                                    \
    asm volatile("mma.sync.aligned.m16n8k16.row.col.f32.f16.f16.f32 "         \
                 "{%0,%1,%2,%3}, {%4,%5,%6,%7}, {%8,%9}, {%0,%1,%2,%3};"      \
                 : "+f"((ap)[0]), "+f"((ap)[1]), "+f"((ap)[2]), "+f"((ap)[3]) \
                 : "r"((a)[0]), "r"((a)[1]), "r"((a)[2]), "r"((a)[3]),        \
                   "r"(b0), "r"(b1))

__device__ __forceinline__ unsigned pack_h2(float s0, float s1) {
    __half2 h = __floats2half2_rn(s0, s1);
    return *reinterpret_cast<unsigned*>(&h);
}
__device__ __forceinline__ void split_pair(float s0, float s1,
                                           unsigned& hp, unsigned& lp) {
    __half h0 = __float2half(s0), h1 = __float2half(s1);
    __half2 hh = __halves2half2(h0, h1);
    hp = *reinterpret_cast<unsigned*>(&hh);
    lp = pack_h2(s0 - __half2float(h0), s1 - __half2float(h1));
}

// ---------------------------------------------------------------------------
// x NCHW fp32 -> NHWC fp32 + fp16
// ---------------------------------------------------------------------------
__global__ void k_xT(const float* __restrict__ x) {
    __shared__ float t[32][33];
    int bx = blockIdx.x;                    // 4096 = b(4) * cblk(8) * pxblk(128)
    int pxb = bx & 127, cb = (bx >> 7) & 7, b = bx >> 10;
    int tx = threadIdx.x & 31, ty = threadIdx.x >> 5;
#pragma unroll
    for (int i = 0; i < 4; i++) {
        int c = cb * 32 + ty + i * 8;
        t[ty + i * 8][tx] = x[(((size_t)(b * 256 + c)) << 12) + pxb * 32 + tx];
    }
    __syncthreads();
#pragma unroll
    for (int i = 0; i < 4; i++) {
        int px = pxb * 32 + ty + i * 8;
        float v = t[tx][ty + i * 8];
        size_t dst = (((size_t)b << 12) + px) * 256 + cb * 32 + tx;
        g_xT[dst] = v;
        g_xH[dst] = __float2half(v);
    }
}

// ---------------------------------------------------------------------------
// main weight [O][C][3][3] -> fp16 [ci][o][k32];  ci = tap*8+cb, c = cb*32+k
// ---------------------------------------------------------------------------
__global__ void k_prepW(const float* __restrict__ w) {
    int o = blockIdx.x;
    for (int idx = threadIdx.x; idx < 2304; idx += 256) {
        int ci = idx >> 5, k = idx & 31;
        int tap = ci >> 3, c = ((ci & 7) << 5) + k;
        g_wF16[(size_t)ci * 8192 + o * 32 + k] =
            __float2half(w[o * 2304 + c * 9 + tap]);
    }
}

// ---------------------------------------------------------------------------
// offset weight [27][C][3][3] -> fp16 [ci][o(32, >=27 zero)][k32]
// ---------------------------------------------------------------------------
__global__ void k_offW(const float* __restrict__ wof) {
    int ci = blockIdx.x;
    int tap = ci >> 3, cb = ci & 7;
    for (int i = threadIdx.x; i < 1024; i += 256) {
        int o = i >> 5, k = i & 31;
        int c = (cb << 5) + k;
        float v = (o < 27) ? wof[o * 2304 + c * 9 + tap] : 0.f;
        g_wOf[ci * 1024 + i] = __float2half(v);
    }
}

// ---------------------------------------------------------------------------
// Fused kernel. Grid 128 = (b, 32 px-tiles of 128). 512 threads.
// SMEM (dynamic, 118784 B):
//   SA[buf][term]: 128 rows x 80B = 10240 each  ->  [0, 40960)
//   SB[buf]:       256 rows x 80B = 20480 each  ->  [40960, 81920)
//     (phase1 uses first 2560 of each SB buf; om scratch 128x32 f32 at 40960)
//   META_I: idx[9][128][4] int   -> [81920, 100352)
//   META_W: wgt[9][128][4] float -> [100352, 118784)
// ---------------------------------------------------------------------------
#define SA(buf, term) ((buf) * 20480 + (term) * 10240)
#define SB(buf)       (40960 + (buf) * 20480)
#define META_I        81920
#define META_W        100352
#define SMEM_TOTAL    118784

__global__ __launch_bounds__(512, 1) void k_mainTC(const float* __restrict__ bof,
                                                   const float* __restrict__ bias) {
    extern __shared__ char sm[];
    unsigned smb = smem_u32(sm);
    int tid = threadIdx.x, lane = tid & 31, wid = tid >> 5;
    int b = blockIdx.x >> 5;
    int tile = blockIdx.x & 31;
    int p0 = tile << 7;

    int px = tid >> 2, oct = tid & 3;     // A staging role (both phases)
    unsigned aoff = (unsigned)((lane & 15) * 80 + (lane >> 4) * 16);
    unsigned boff = (unsigned)((lane & 7) * 80 + ((lane >> 3) & 1) * 16 +
                               (lane >> 4) * 640);
    unsigned ao = (unsigned)(px * 80 + oct * 16);

    // =======================================================================
    // Phase 1: offset conv HMMA (fp16 im2col A, single term).
    // 16 warps = (wm1 0..7) x (wn1 0..1), warp tile 16x16.
    // =======================================================================
    {
        int wm1 = wid & 7, wn1 = wid >> 3;
        float acc1[2][4];
#pragma unroll
        for (int i = 0; i < 2; i++)
#pragma unroll
            for (int j = 0; j < 4; j++) acc1[i][j] = 0.f;

        const __half* xh = g_xH + ((size_t)b << 20);
        int gp = p0 + px, h = gp >> 6, w = gp & 63;
        uint4 qA;
        auto loadA1 = [&](int ci) {
            int tap = ci >> 3, cb = ci & 7;
            int py = h + tap / 3 - 1, pxx = w + tap % 3 - 1;
            if (py >= 0 && py < 64 && pxx >= 0 && pxx < 64) {
                qA = *(const uint4*)(xh + (((size_t)(py * 64 + pxx)) << 8) +
                                     (cb << 5) + (oct << 3));
            } else {
                qA = make_uint4(0u, 0u, 0u, 0u);
            }
        };
        auto loadB1 = [&](int ci, int buf) {
            if (tid < 128) {
                int row = tid >> 2, q = tid & 3;
                CP16(smb + SB(buf) + row * 80 + q * 16,
                     g_wOf + ci * 1024 + row * 32 + q * 8);
            }
            CP_COMMIT();
        };

        loadA1(0);
        loadB1(0, 0);
#pragma unroll 1
        for (int ci = 0; ci < 72; ci++) {
            int buf = ci & 1;
            *(uint4*)(sm + SA(buf, 0) + ao) = qA;
            CP_WAIT0();
            __syncthreads();
            if (ci < 71) { loadA1(ci + 1); loadB1(ci + 1, buf ^ 1); }
            unsigned aB = smb + (unsigned)(buf * 20480 + wm1 * 1280) + aoff;
            unsigned bB = smb + (unsigned)SB(buf) + (unsigned)(wn1 * 1280) + boff;
#pragma unroll
            for (int ks = 0; ks < 2; ks++) {
                unsigned ah[4], bh[4];
                LDSM4(ah, aB + ks * 32);
                LDSM4(bh, bB + ks * 32);
                MMA(acc1[0], ah, bh[0], bh[1]);
                MMA(acc1[1], ah, bh[2], bh[3]);
            }
            // no end-of-loop barrier: next iter's mid barrier orders reuse
        }
        __syncthreads();
        // om scratch (128 x 32 f32) at sm+40960
        float* som = (float*)(sm + 40960);
        {
            int row = wm1 * 16 + (lane >> 2);
            int col = wn1 * 16 + (lane & 3) * 2;
#pragma unroll
            for (int nt = 0; nt < 2; nt++) {
                int c = col + nt * 8;
                som[row * 32 + c] = acc1[nt][0];
                som[row * 32 + c + 1] = acc1[nt][1];
                som[(row + 8) * 32 + c] = acc1[nt][2];
                som[(row + 8) * 32 + c + 1] = acc1[nt][3];
            }
        }
        __syncthreads();
        // bilinear meta -> smem META
        int* sIdx = (int*)(sm + META_I);
        float* sWgt = (float*)(sm + META_W);
        for (int idx = tid; idx < 1152; idx += 512) {
            int pr = idx / 9, k = idx - pr * 9;
            float ay = som[pr * 32 + k] + __ldg(bof + k);
            float ax = som[pr * 32 + k + 9] + __ldg(bof + k + 9);
            float am = som[pr * 32 + k + 18] + __ldg(bof + k + 18);
            float m = 1.f / (1.f + __expf(-am));
            int gp2 = p0 + pr, hh = gp2 >> 6, ww = gp2 & 63;
            float py = (float)(hh + k / 3 - 1) + ay;
            float pxx = (float)(ww + (k - (k / 3) * 3) - 1) + ax;
            float y0f = floorf(py), x0f = floorf(pxx);
            float wy1 = py - y0f, wx1 = pxx - x0f;
            int y0 = (int)y0f, x0 = (int)x0f;
            int mo = (k * 128 + pr) * 4;
#pragma unroll
            for (int j = 0; j < 4; j++) {
                int dy = j >> 1, dx = j & 1;
                int yy = y0 + dy, xx = x0 + dx;
                float wv = (dy ? wy1 : 1.f - wy1) * (dx ? wx1 : 1.f - wx1);
                bool valid = (yy >= 0) && (yy < 64) && (xx >= 0) && (xx < 64);
                int yc = min(max(yy, 0), 63), xc = min(max(xx, 0), 63);
                sIdx[mo + j] = yc * 64 + xc;
                sWgt[mo + j] = valid ? wv * m : 0.f;
            }
        }
        __syncthreads();
    }

    // =======================================================================
    // Phase 2: main deformable GEMM. 16 warps = (wm 0..3) x (wn 0..3), 32x64.
    // fp32 raw-corner prefetch split around MMA ksteps; A hi/lo fp16 split.
    // =======================================================================
    int wm = wid & 3, wn = wid >> 2;
    float acc[64];
#pragma unroll
    for (int i = 0; i < 64; i++) acc[i] = 0.f;

    const float* xb = g_xT + ((size_t)b << 20);
    int4 mi;
    float4 mw;
    float sampA[8];
    float4 qa0, qa1, qb0, qb1;   // two raw corners (8 ch each)
    const int* sIdx = (const int*)(sm + META_I);
    const float* sWgt = (const float*)(sm + META_W);

    auto meta = [&](int tap) {
        mi = *(const int4*)(sIdx + (tap * 128 + px) * 4);
        mw = *(const float4*)(sWgt + (tap * 128 + px) * 4);
    };
    auto loadB = [&](int ci, int buf) {
        if (tid < 256) {
            const __half* g = g_wF16 + (size_t)ci * 8192 + tid * 32;
            unsigned s = smb + SB(buf) + tid * 80;
            CP16(s, g); CP16(s + 16, g + 8);
            CP16(s + 32, g + 16); CP16(s + 48, g + 24);
        }
        CP_COMMIT();
    };

    // prologue: compute sampA for chunk 0 (eager; one-time cost)
    meta(0);
    {
        const float* base = xb + oct * 8;
        const float* p = base + ((size_t)mi.x << 8);
        qa0 = *(const float4*)p; qa1 = *(const float4*)(p + 4);
        p = base + ((size_t)mi.y << 8);
        qb0 = *(const float4*)p; qb1 = *(const float4*)(p + 4);
        sampA[0] = fmaf(mw.y, qb0.x, mw.x * qa0.x);
        sampA[1] = fmaf(mw.y, qb0.y, mw.x * qa0.y);
        sampA[2] = fmaf(mw.y, qb0.z, mw.x * qa0.z);
        sampA[3] = fmaf(mw.y, qb0.w, mw.x * qa0.w);
        sampA[4] = fmaf(mw.y, qb1.x, mw.x * qa1.x);
        sampA[5] = fmaf(mw.y, qb1.y, mw.x * qa1.y);
        sampA[6] = fmaf(mw.y, qb1.z, mw.x * qa1.z);
        sampA[7] = fmaf(mw.y, qb1.w, mw.x * qa1.w);
        p = base + ((size_t)mi.z << 8);
        qa0 = *(const float4*)p; qa1 = *(const float4*)(p + 4);
        p = base + ((size_t)mi.w << 8);
        qb0 = *(const float4*)p; qb1 = *(const float4*)(p + 4);
        sampA[0] = fmaf(mw.w, qb0.x, fmaf(mw.z, qa0.x, sampA[0]));
        sampA[1] = fmaf(mw.w, qb0.y, fmaf(mw.z, qa0.y, sampA[1]));
        sampA[2] = fmaf(mw.w, qb0.z, fmaf(mw.z, qa0.z, sampA[2]));
        sampA[3] = fmaf(mw.w, qb0.w, fmaf(mw.z, qa0.w, sampA[3]));
        sampA[4] = fmaf(mw.w, qb1.x, fmaf(mw.z, qa1.x, sampA[4]));
        sampA[5] = fmaf(mw.w, qb1.y, fmaf(mw.z, qa1.y, sampA[5]));
        sampA[6] = fmaf(mw.w, qb1.z, fmaf(mw.z, qa1.z, sampA[6]));
        sampA[7] = fmaf(mw.w, qb1.w, fmaf(mw.z, qa1.w, sampA[7]));
    }
    loadB(0, 0);

#pragma unroll 1
    for (int ci = 0; ci < 72; ci++) {
        int buf = ci & 1;
        // split & store A(ci) from sampA
        {
            unsigned hp[4], lp[4];
            split_pair(sampA[0], sampA[1], hp[0], lp[0]);
            split_pair(sampA[2], sampA[3], hp[1], lp[1]);
            split_pair(sampA[4], sampA[5], hp[2], lp[2]);
            split_pair(sampA[6], sampA[7], hp[3], lp[3]);
            *(uint4*)(sm + SA(buf, 0) + ao) = make_uint4(hp[0], hp[1], hp[2], hp[3]);
            *(uint4*)(sm + SA(buf, 1) + ao) = make_uint4(lp[0], lp[1], lp[2], lp[3]);
        }
        CP_WAIT0();
        __syncthreads();

        int cn = ci + 1;
        bool more = cn < 72;
        const float* base = nullptr;
        if (more) {
            if ((cn & 7) == 0) meta(cn >> 3);
            base = xb + ((cn & 7) << 5) + oct * 8;
            // issue raw loads for corners 0,1 (consumed after MMA ks=0)
            const float* p = base + ((size_t)mi.x << 8);
            qa0 = *(const float4*)p; qa1 = *(const float4*)(p + 4);
            p = base + ((size_t)mi.y << 8);
            qb0 = *(const float4*)p; qb1 = *(const float4*)(p + 4);
            loadB(cn, buf ^ 1);
        }

        unsigned ab = smb + (unsigned)(buf * 20480 + wm * 2560) + aoff;
        unsigned bb = smb + (unsigned)(SB(buf) + wn * 5120) + boff;
        // ---- MMA kstep 0 ----
        {
            unsigned ah0[4], ah1[4], al0[4], al1[4];
            LDSM4(ah0, ab);
            LDSM4(ah1, ab + 1280);
            LDSM4(al0, ab + 10240);
            LDSM4(al1, ab + 11520);
#pragma unroll
            for (int ntp = 0; ntp < 4; ntp++) {
                unsigned bh[4];
                LDSM4(bh, bb + ntp * 1280);
                float* a00 = &acc[(ntp * 2) * 4];
                float* a01 = &acc[(ntp * 2 + 1) * 4];
                float* a10 = &acc[(8 + ntp * 2) * 4];
                float* a11 = &acc[(8 + ntp * 2 + 1) * 4];
                MMA(a00, ah0, bh[0], bh[1]);
                MMA(a01, ah0, bh[2], bh[3]);
                MMA(a10, ah1, bh[0], bh[1]);
                MMA(a11, ah1, bh[2], bh[3]);
                MMA(a00, al0, bh[0], bh[1]);
                MMA(a01, al0, bh[2], bh[3]);
                MMA(a10, al1, bh[0], bh[1]);
                MMA(a11, al1, bh[2], bh[3]);
            }
        }
        // weight corners 0,1 -> sampA; issue raw loads for corners 2,3
        if (more) {
            sampA[0] = fmaf(mw.y, qb0.x, mw.x * qa0.x);
            sampA[1] = fmaf(mw.y, qb0.y, mw.x * qa0.y);
            sampA[2] = fmaf(mw.y, qb0.z, mw.x * qa0.z);
            sampA[3] = fmaf(mw.y, qb0.w, mw.x * qa0.w);
            sampA[4] = fmaf(mw.y, qb1.x, mw.x * qa1.x);
            sampA[5] = fmaf(mw.y, qb1.y, mw.x * qa1.y);
            sampA[6] = fmaf(mw.y, qb1.z, mw.x * qa1.z);
            sampA[7] = fmaf(mw.y, qb1.w, mw.x * qa1.w);
            const float* p = base + ((size_t)mi.z << 8);
            qa0 = *(const float4*)p; qa1 = *(const float4*)(p + 4);
            p = base + ((size_t)mi.w << 8);
            qb0 = *(const float4*)p; qb1 = *(const float4*)(p + 4);
        }
        // ---- MMA kstep 1 ----
        {
            unsigned ah0[4], ah1[4], al0[4], al1[4];
            LDSM4(ah0, ab + 32);
            LDSM4(ah1, ab + 1312);
            LDSM4(al0, ab + 10272);
            LDSM4(al1, ab + 11552);
#pragma unroll
            for (int ntp = 0; ntp < 4; ntp++) {
                unsigned bh[4];
                LDSM4(bh, bb + ntp * 1280 + 32);
                float* a00 = &acc[(ntp * 2) * 4];
                float* a01 = &acc[(ntp * 2 + 1) * 4];
                float* a10 = &acc[(8 + ntp * 2) * 4];
                float* a11 = &acc[(8 + ntp * 2 + 1) * 4];
                MMA(a00, ah0, bh[0], bh[1]);
                MMA(a01, ah0, bh[2], bh[3]);
                MMA(a10, ah1, bh[0], bh[1]);
                MMA(a11, ah1, bh[2], bh[3]);
                MMA(a00, al0, bh[0], bh[1]);
                MMA(a01, al0, bh[2], bh[3]);
                MMA(a10, al1, bh[0], bh[1]);
                MMA(a11, al1, bh[2], bh[3]);
            }
        }
        // weight corners 2,3 -> sampA
        if (more) {
            sampA[0] = fmaf(mw.w, qb0.x, fmaf(mw.z, qa0.x, sampA[0]));
            sampA[1] = fmaf(mw.w, qb0.y, fmaf(mw.z, qa0.y, sampA[1]));
            sampA[2] = fmaf(mw.w, qb0.z, fmaf(mw.z, qa0.z, sampA[2]));
            sampA[3] = fmaf(mw.w, qb0.w, fmaf(mw.z, qa0.w, sampA[3]));
            sampA[4] = fmaf(mw.w, qb1.x, fmaf(mw.z, qa1.x, sampA[4]));
            sampA[5] = fmaf(mw.w, qb1.y, fmaf(mw.z, qa1.y, sampA[5]));
            sampA[6] = fmaf(mw.w, qb1.z, fmaf(mw.z, qa1.z, sampA[6]));
            sampA[7] = fmaf(mw.w, qb1.w, fmaf(mw.z, qa1.w, sampA[7]));
        }
        // no end-of-loop barrier (mid barrier of next iter orders reuse)
    }
    __syncthreads();

    // ---- epilogue: bias add, store, fused GN partial stats ----
    float pg[4] = {0.f, 0.f, 0.f, 0.f};
    float pq[4] = {0.f, 0.f, 0.f, 0.f};
    int pxb = p0 + wm * 32 + (lane >> 2);
#pragma unroll
    for (int mt = 0; mt < 2; mt++) {
#pragma unroll
        for (int nt = 0; nt < 8; nt++) {
            float* ap = &acc[(mt * 8 + nt) * 4];
            int o = wn * 64 + nt * 8 + (lane & 3) * 2;
            float bv0 = __ldg(bias + o), bv1 = __ldg(bias + o + 1);
            int pxm = pxb + mt * 16;
            size_t r0 = (((size_t)(b * 256 + o)) << 12) + pxm;
            size_t r1 = r0 + 4096;
            float v0 = ap[0] + bv0, v1 = ap[1] + bv1;
            float v2 = ap[2] + bv0, v3 = ap[3] + bv1;
            g_conv[r0] = v0;
            g_conv[r1] = v1;
            g_conv[r0 + 8] = v2;
            g_conv[r1 + 8] = v3;
            int j = nt >> 1;
            pg[j] += v0 + v1 + v2 + v3;
            pq[j] += v0 * v0 + v1 * v1 + v2 * v2 + v3 * v3;
        }
    }
#pragma unroll
    for (int j = 0; j < 4; j++) {
#pragma unroll
        for (int s = 16; s > 0; s >>= 1) {
            pg[j] += __shfl_down_sync(0xFFFFFFFFu, pg[j], s);
            pq[j] += __shfl_down_sync(0xFFFFFFFFu, pq[j], s);
        }
    }
    float* red = (float*)sm;   // 16 warps x 8 floats
    if (lane == 0) {
#pragma unroll
        for (int j = 0; j < 4; j++) {
            red[wid * 8 + j] = pg[j];
            red[wid * 8 + 4 + j] = pq[j];
        }
    }
    __syncthreads();
    if (tid < 32) {
        int group = tid >> 1, which = tid & 1;
        int wnb = group >> 2;
        float v = 0.f;
#pragma unroll
        for (int wmi = 0; wmi < 4; wmi++)
            v += red[(wnb * 4 + wmi) * 8 + (group & 3) + 4 * which];
        if (which == 0) g_psum[(b * 16 + group) * 32 + tile] = v;
        else            g_pssum[(b * 16 + group) * 32 + tile] = v;
    }
}

// ---------------------------------------------------------------------------
// GN stats finalize: 64 blocks x 32 threads
// ---------------------------------------------------------------------------
__global__ void k_statsF() {
    int bg = blockIdx.x, t = threadIdx.x;
    float s = g_psum[bg * 32 + t];
    float q = g_pssum[bg * 32 + t];
#pragma unroll
    for (int o = 16; o > 0; o >>= 1) {
        s += __shfl_down_sync(0xFFFFFFFFu, s, o);
        q += __shfl_down_sync(0xFFFFFFFFu, q, o);
    }
    if (t == 0) {
        float mu = s * (1.f / 65536.f);
        float var = q * (1.f / 65536.f) - mu * mu;
        g_mu[bg] = mu;
        g_rs[bg] = rsqrtf(var + 1e-5f);
    }
}

// ---------------------------------------------------------------------------
// Normalize + affine -> d_out.  2048 blocks x 256 thr x 2 float4.
// ---------------------------------------------------------------------------
__global__ void k_norm(const float* __restrict__ gamma,
                       const float* __restrict__ beta,
                       float* __restrict__ out) {
    int i = blockIdx.x * 512 + threadIdx.x;
#pragma unroll
    for (int t = 0; t < 2; t++, i += 256) {
        float4 v = ((const float4*)g_conv)[i];
        int bc = i >> 10;
        int c = bc & 255, b = bc >> 8;
        int bg = b * 16 + (c >> 4);
        float sc = g_rs[bg] * gamma[c];
        float sh = beta[c] - g_mu[bg] * sc;
        v.x = v.x * sc + sh;
        v.y = v.y * sc + sh;
        v.z = v.z * sc + sh;
        v.w = v.w * sc + sh;
        ((float4*)out)[i] = v;
    }
}

// ---------------------------------------------------------------------------
extern "C" void kernel_launch(void* const* d_in, const int* in_sizes, int n_in,
                              void* d_out, int out_size) {
    const float* x = nullptr;
    const float* w_off = nullptr;
    const float* b_off = nullptr;
    const float* weight = nullptr;
    const float* v256[3] = {nullptr, nullptr, nullptr};
    int n256 = 0;
    for (int i = 0; i < n_in; i++) {
        int s = in_sizes[i];
        const float* ptr = (const float*)d_in[i];
        if (s == 4194304) x = ptr;
        else if (s == 62208) w_off = ptr;
        else if (s == 27) b_off = ptr;
        else if (s == 589824) weight = ptr;
        else if (s == 256 && n256 < 3) v256[n256++] = ptr;
    }
    const float* bias  = v256[0];
    const float* gamma = v256[1];
    const float* beta  = v256[2];
    float* out = (float*)d_out;

    cudaFuncSetAttribute(k_mainTC, cudaFuncAttributeMaxDynamicSharedMemorySize,
                         SMEM_TOTAL);

    k_xT<<<4096, 256>>>(x);
    k_prepW<<<256, 256>>>(weight);
    k_offW<<<72, 256>>>(w_off);
    k_mainTC<<<128, 512, SMEM_TOTAL>>>(b_off, bias);
    k_statsF<<<64, 32>>>();
    k_norm<<<2048, 256>>>(gamma, beta, out);
}

// round 13
// speedup vs baseline: 1.9051x; 1.2024x over previous
#include <cuda_runtime.h>
#include <cuda_fp16.h>
#include <cstdint>

// ---------------------------------------------------------------------------
// DCNv2 + GroupNorm16.  B=4, Cin=Cout=256, H=W=64, K=3, s=1, p=1, g=16.
// Fused tensor-core kernel (M=128 tiles, 512 thr, grid 128):
//  phase1 = offset conv HMMA (fp16 im2col A) + bilinear meta in smem;
//  phase2 = deformable-sampled HMMA GEMM, A single fp16, B single fp16
//  (fp32 gathers + fp32 sampling; software load/use split hides LDG under
//  MMA). One barrier per chunk. GN partial stats fused in epilogue.
// compute_103 baseline PTX only.
// ---------------------------------------------------------------------------

// ---- device-global scratch -------------------------------------------------
__device__ float  g_xT[4 * 4096 * 256];       // x NHWC fp32 (phase2 gathers)
__device__ __half g_xH[4 * 4096 * 256];       // x NHWC fp16 (phase1 im2col)
__device__ __half g_wF16[72 * 256 * 32];      // main weight fp16 [ci][o][k]
__device__ __half g_wOf[72 * 32 * 32];        // offset weight fp16 [ci][o32][k]
__device__ float  g_conv[4 * 256 * 4096];     // conv out (pre-GN)
__device__ float  g_psum[64 * 32];            // per-(bg,tile) partial sums
__device__ float  g_pssum[64 * 32];
__device__ float  g_mu[64];
__device__ float  g_rs[64];

// ---- PTX helpers ----------------------------------------------------------
__device__ __forceinline__ unsigned smem_u32(const void* p) {
    unsigned a;
    asm("{ .reg .u64 t; cvta.to.shared.u64 t, %1; cvt.u32.u64 %0, t; }"
        : "=r"(a) : "l"(p));
    return a;
}
#define CP16(s, g) asm volatile("cp.async.cg.shared.global [%0], [%1], 16;" :: "r"(s), "l"(g) : "memory")
#define CP_COMMIT() asm volatile("cp.async.commit_group;" ::: "memory")
#define CP_WAIT0()  asm volatile("cp.async.wait_group 0;" ::: "memory")

#define LDSM4(r, addr)                                                        \
    asm volatile("ldmatrix.sync.aligned.m8n8.x4.shared.b16 {%0,%1,%2,%3}, [%4];" \
                 : "=r"((r)[0]), "=r"((r)[1]), "=r"((r)[2]), "=r"((r)[3])     \
                 : "r"(addr))

#define MMA(ap, a, b0, b1)                                                    \
    asm volatile("mma.sync.aligned.m16n8k16.row.col.f32.f16.f16.f32 "         \
                 "{%0,%1,%2,%3}, {%4,%5,%6,%7}, {%8,%9}, {%0,%1,%2,%3};"      \
                 : "+f"((ap)[0]), "+f"((ap)[1]), "+f"((ap)[2]), "+f"((ap)[3]) \
                 : "r"((a)[0]), "r"((a)[1]), "r"((a)[2]), "r"((a)[3]),        \
                   "r"(b0), "r"(b1))

__device__ __forceinline__ unsigned pack_h2(float s0, float s1) {
    __half2 h = __floats2half2_rn(s0, s1);
    return *reinterpret_cast<unsigned*>(&h);
}

// ---------------------------------------------------------------------------
// x NCHW fp32 -> NHWC fp32 + fp16
// ---------------------------------------------------------------------------
__global__ void k_xT(const float* __restrict__ x) {
    __shared__ float t[32][33];
    int bx = blockIdx.x;                    // 4096 = b(4) * cblk(8) * pxblk(128)
    int pxb = bx & 127, cb = (bx >> 7) & 7, b = bx >> 10;
    int tx = threadIdx.x & 31, ty = threadIdx.x >> 5;
#pragma unroll
    for (int i = 0; i < 4; i++) {
        int c = cb * 32 + ty + i * 8;
        t[ty + i * 8][tx] = x[(((size_t)(b * 256 + c)) << 12) + pxb * 32 + tx];
    }
    __syncthreads();
#pragma unroll
    for (int i = 0; i < 4; i++) {
        int px = pxb * 32 + ty + i * 8;
        float v = t[tx][ty + i * 8];
        size_t dst = (((size_t)b << 12) + px) * 256 + cb * 32 + tx;
        g_xT[dst] = v;
        g_xH[dst] = __float2half(v);
    }
}

// ---------------------------------------------------------------------------
// main weight [O][C][3][3] -> fp16 [ci][o][k32];  ci = tap*8+cb, c = cb*32+k
// ---------------------------------------------------------------------------
__global__ void k_prepW(const float* __restrict__ w) {
    int o = blockIdx.x;
    for (int idx = threadIdx.x; idx < 2304; idx += 256) {
        int ci = idx >> 5, k = idx & 31;
        int tap = ci >> 3, c = ((ci & 7) << 5) + k;
        g_wF16[(size_t)ci * 8192 + o * 32 + k] =
            __float2half(w[o * 2304 + c * 9 + tap]);
    }
}

// ---------------------------------------------------------------------------
// offset weight [27][C][3][3] -> fp16 [ci][o(32, >=27 zero)][k32]
// ---------------------------------------------------------------------------
__global__ void k_offW(const float* __restrict__ wof) {
    int ci = blockIdx.x;
    int tap = ci >> 3, cb = ci & 7;
    for (int i = threadIdx.x; i < 1024; i += 256) {
        int o = i >> 5, k = i & 31;
        int c = (cb << 5) + k;
        float v = (o < 27) ? wof[o * 2304 + c * 9 + tap] : 0.f;
        g_wOf[ci * 1024 + i] = __float2half(v);
    }
}

// ---------------------------------------------------------------------------
// Fused kernel. Grid 128 = (b, 32 px-tiles of 128). 512 threads.
// SMEM (dynamic, 98304 B):
//   SA[buf]: 128 rows x 80B = 10240 each  ->  [0, 20480)
//   SB[buf]: 256 rows x 80B = 20480 each  ->  [20480, 61440)
//     (phase1 uses first 2560 of each SB buf; om scratch 128x32 f32 at 20480)
//   META_I: idx[9][128][4] int   -> [61440, 79872)
//   META_W: wgt[9][128][4] float -> [79872, 98304)
// ---------------------------------------------------------------------------
#define SA(buf)   ((buf) * 10240)
#define SB(buf)   (20480 + (buf) * 20480)
#define META_I    61440
#define META_W    79872
#define SMEM_TOTAL 98304

__global__ __launch_bounds__(512, 1) void k_mainTC(const float* __restrict__ bof,
                                                   const float* __restrict__ bias) {
    extern __shared__ char sm[];
    unsigned smb = smem_u32(sm);
    int tid = threadIdx.x, lane = tid & 31, wid = tid >> 5;
    int b = blockIdx.x >> 5;
    int tile = blockIdx.x & 31;
    int p0 = tile << 7;

    int px = tid >> 2, oct = tid & 3;     // A staging role (both phases)
    unsigned aoff = (unsigned)((lane & 15) * 80 + (lane >> 4) * 16);
    unsigned boff = (unsigned)((lane & 7) * 80 + ((lane >> 3) & 1) * 16 +
                               (lane >> 4) * 640);
    unsigned ao = (unsigned)(px * 80 + oct * 16);

    // =======================================================================
    // Phase 1: offset conv HMMA (fp16 im2col A, single term).
    // 16 warps = (wm1 0..7) x (wn1 0..1), warp tile 16x16.
    // =======================================================================
    {
        int wm1 = wid & 7, wn1 = wid >> 3;
        float acc1[2][4];
#pragma unroll
        for (int i = 0; i < 2; i++)
#pragma unroll
            for (int j = 0; j < 4; j++) acc1[i][j] = 0.f;

        const __half* xh = g_xH + ((size_t)b << 20);
        int gp = p0 + px, h = gp >> 6, w = gp & 63;
        uint4 qA;
        auto loadA1 = [&](int ci) {
            int tap = ci >> 3, cb = ci & 7;
            int py = h + tap / 3 - 1, pxx = w + tap % 3 - 1;
            if (py >= 0 && py < 64 && pxx >= 0 && pxx < 64) {
                qA = *(const uint4*)(xh + (((size_t)(py * 64 + pxx)) << 8) +
                                     (cb << 5) + (oct << 3));
            } else {
                qA = make_uint4(0u, 0u, 0u, 0u);
            }
        };
        auto loadB1 = [&](int ci, int buf) {
            if (tid < 128) {
                int row = tid >> 2, q = tid & 3;
                CP16(smb + SB(buf) + row * 80 + q * 16,
                     g_wOf + ci * 1024 + row * 32 + q * 8);
            }
            CP_COMMIT();
        };

        loadA1(0);
        loadB1(0, 0);
#pragma unroll 1
        for (int ci = 0; ci < 72; ci++) {
            int buf = ci & 1;
            *(uint4*)(sm + SA(buf) + ao) = qA;
            CP_WAIT0();
            __syncthreads();
            if (ci < 71) { loadA1(ci + 1); loadB1(ci + 1, buf ^ 1); }
            unsigned aB = smb + (unsigned)(buf * 10240 + wm1 * 1280) + aoff;
            unsigned bB = smb + (unsigned)SB(buf) + (unsigned)(wn1 * 1280) + boff;
#pragma unroll
            for (int ks = 0; ks < 2; ks++) {
                unsigned ah[4], bh[4];
                LDSM4(ah, aB + ks * 32);
                LDSM4(bh, bB + ks * 32);
                MMA(acc1[0], ah, bh[0], bh[1]);
                MMA(acc1[1], ah, bh[2], bh[3]);
            }
            // no end-of-loop barrier: next iter's mid barrier orders reuse
        }
        __syncthreads();
        // om scratch (128 x 32 f32) at sm+20480
        float* som = (float*)(sm + 20480);
        {
            int row = wm1 * 16 + (lane >> 2);
            int col = wn1 * 16 + (lane & 3) * 2;
#pragma unroll
            for (int nt = 0; nt < 2; nt++) {
                int c = col + nt * 8;
                som[row * 32 + c] = acc1[nt][0];
                som[row * 32 + c + 1] = acc1[nt][1];
                som[(row + 8) * 32 + c] = acc1[nt][2];
                som[(row + 8) * 32 + c + 1] = acc1[nt][3];
            }
        }
        __syncthreads();
        // bilinear meta -> smem META
        int* sIdx = (int*)(sm + META_I);
        float* sWgt = (float*)(sm + META_W);
        for (int idx = tid; idx < 1152; idx += 512) {
            int pr = idx / 9, k = idx - pr * 9;
            float ay = som[pr * 32 + k] + __ldg(bof + k);
            float ax = som[pr * 32 + k + 9] + __ldg(bof + k + 9);
            float am = som[pr * 32 + k + 18] + __ldg(bof + k + 18);
            float m = 1.f / (1.f + __expf(-am));
            int gp2 = p0 + pr, hh = gp2 >> 6, ww = gp2 & 63;
            float py = (float)(hh + k / 3 - 1) + ay;
            float pxx = (float)(ww + (k - (k / 3) * 3) - 1) + ax;
            float y0f = floorf(py), x0f = floorf(pxx);
            float wy1 = py - y0f, wx1 = pxx - x0f;
            int y0 = (int)y0f, x0 = (int)x0f;
            int mo = (k * 128 + pr) * 4;
#pragma unroll
            for (int j = 0; j < 4; j++) {
                int dy = j >> 1, dx = j & 1;
                int yy = y0 + dy, xx = x0 + dx;
                float wv = (dy ? wy1 : 1.f - wy1) * (dx ? wx1 : 1.f - wx1);
                bool valid = (yy >= 0) && (yy < 64) && (xx >= 0) && (xx < 64);
                int yc = min(max(yy, 0), 63), xc = min(max(xx, 0), 63);
                sIdx[mo + j] = yc * 64 + xc;
                sWgt[mo + j] = valid ? wv * m : 0.f;
            }
        }
        __syncthreads();
    }

    // =======================================================================
    // Phase 2: main deformable GEMM. 16 warps = (wm 0..3) x (wn 0..3), 32x64.
    // fp32 raw-corner prefetch split around MMA ksteps; A single fp16.
    // =======================================================================
    int wm = wid & 3, wn = wid >> 2;
    float acc[64];
#pragma unroll
    for (int i = 0; i < 64; i++) acc[i] = 0.f;

    const float* xb = g_xT + ((size_t)b << 20);
    int4 mi;
    float4 mw;
    float sampA[8];
    float4 qa0, qa1, qb0, qb1;   // two raw corners (8 ch each)
    const int* sIdx = (const int*)(sm + META_I);
    const float* sWgt = (const float*)(sm + META_W);

    auto meta = [&](int tap) {
        mi = *(const int4*)(sIdx + (tap * 128 + px) * 4);
        mw = *(const float4*)(sWgt + (tap * 128 + px) * 4);
    };
    auto loadB = [&](int ci, int buf) {
        if (tid < 256) {
            const __half* g = g_wF16 + (size_t)ci * 8192 + tid * 32;
            unsigned s = smb + SB(buf) + tid * 80;
            CP16(s, g); CP16(s + 16, g + 8);
            CP16(s + 32, g + 16); CP16(s + 48, g + 24);
        }
        CP_COMMIT();
    };

    // prologue: compute sampA for chunk 0 (eager; one-time cost)
    meta(0);
    {
        const float* base = xb + oct * 8;
        const float* p = base + ((size_t)mi.x << 8);
        qa0 = *(const float4*)p; qa1 = *(const float4*)(p + 4);
        p = base + ((size_t)mi.y << 8);
        qb0 = *(const float4*)p; qb1 = *(const float4*)(p + 4);
        sampA[0] = fmaf(mw.y, qb0.x, mw.x * qa0.x);
        sampA[1] = fmaf(mw.y, qb0.y, mw.x * qa0.y);
        sampA[2] = fmaf(mw.y, qb0.z, mw.x * qa0.z);
        sampA[3] = fmaf(mw.y, qb0.w, mw.x * qa0.w);
        sampA[4] = fmaf(mw.y, qb1.x, mw.x * qa1.x);
        sampA[5] = fmaf(mw.y, qb1.y, mw.x * qa1.y);
        sampA[6] = fmaf(mw.y, qb1.z, mw.x * qa1.z);
        sampA[7] = fmaf(mw.y, qb1.w, mw.x * qa1.w);
        p = base + ((size_t)mi.z << 8);
        qa0 = *(const float4*)p; qa1 = *(const float4*)(p + 4);
        p = base + ((size_t)mi.w << 8);
        qb0 = *(const float4*)p; qb1 = *(const float4*)(p + 4);
        sampA[0] = fmaf(mw.w, qb0.x, fmaf(mw.z, qa0.x, sampA[0]));
        sampA[1] = fmaf(mw.w, qb0.y, fmaf(mw.z, qa0.y, sampA[1]));
        sampA[2] = fmaf(mw.w, qb0.z, fmaf(mw.z, qa0.z, sampA[2]));
        sampA[3] = fmaf(mw.w, qb0.w, fmaf(mw.z, qa0.w, sampA[3]));
        sampA[4] = fmaf(mw.w, qb1.x, fmaf(mw.z, qa1.x, sampA[4]));
        sampA[5] = fmaf(mw.w, qb1.y, fmaf(mw.z, qa1.y, sampA[5]));
        sampA[6] = fmaf(mw.w, qb1.z, fmaf(mw.z, qa1.z, sampA[6]));
        sampA[7] = fmaf(mw.w, qb1.w, fmaf(mw.z, qa1.w, sampA[7]));
    }
    loadB(0, 0);

#pragma unroll 1
    for (int ci = 0; ci < 72; ci++) {
        int buf = ci & 1;
        // pack & store A(ci) from sampA (single fp16 term)
        {
            unsigned hp0 = pack_h2(sampA[0], sampA[1]);
            unsigned hp1 = pack_h2(sampA[2], sampA[3]);
            unsigned hp2 = pack_h2(sampA[4], sampA[5]);
            unsigned hp3 = pack_h2(sampA[6], sampA[7]);
            *(uint4*)(sm + SA(buf) + ao) = make_uint4(hp0, hp1, hp2, hp3);
        }
        CP_WAIT0();
        __syncthreads();

        int cn = ci + 1;
        bool more = cn < 72;
        const float* base = nullptr;
        if (more) {
            if ((cn & 7) == 0) meta(cn >> 3);
            base = xb + ((cn & 7) << 5) + oct * 8;
            // issue raw loads for corners 0,1 (consumed after MMA ks=0)
            const float* p = base + ((size_t)mi.x << 8);
            qa0 = *(const float4*)p; qa1 = *(const float4*)(p + 4);
            p = base + ((size_t)mi.y << 8);
            qb0 = *(const float4*)p; qb1 = *(const float4*)(p + 4);
            loadB(cn, buf ^ 1);
        }

        unsigned ab = smb + (unsigned)(buf * 10240 + wm * 2560) + aoff;
        unsigned bb = smb + (unsigned)(SB(buf) + wn * 5120) + boff;
        // ---- MMA kstep 0 ----
        {
            unsigned ah0[4], ah1[4];
            LDSM4(ah0, ab);
            LDSM4(ah1, ab + 1280);
#pragma unroll
            for (int ntp = 0; ntp < 4; ntp++) {
                unsigned bh[4];
                LDSM4(bh, bb + ntp * 1280);
                MMA(&acc[(ntp * 2) * 4], ah0, bh[0], bh[1]);
                MMA(&acc[(ntp * 2 + 1) * 4], ah0, bh[2], bh[3]);
                MMA(&acc[(8 + ntp * 2) * 4], ah1, bh[0], bh[1]);
                MMA(&acc[(8 + ntp * 2 + 1) * 4], ah1, bh[2], bh[3]);
            }
        }
        // weight corners 0,1 -> sampA; issue raw loads for corners 2,3
        if (more) {
            sampA[0] = fmaf(mw.y, qb0.x, mw.x * qa0.x);
            sampA[1] = fmaf(mw.y, qb0.y, mw.x * qa0.y);
            sampA[2] = fmaf(mw.y, qb0.z, mw.x * qa0.z);
            sampA[3] = fmaf(mw.y, qb0.w, mw.x * qa0.w);
            sampA[4] = fmaf(mw.y, qb1.x, mw.x * qa1.x);
            sampA[5] = fmaf(mw.y, qb1.y, mw.x * qa1.y);
            sampA[6] = fmaf(mw.y, qb1.z, mw.x * qa1.z);
            sampA[7] = fmaf(mw.y, qb1.w, mw.x * qa1.w);
            const float* p = base + ((size_t)mi.z << 8);
            qa0 = *(const float4*)p; qa1 = *(const float4*)(p + 4);
            p = base + ((size_t)mi.w << 8);
            qb0 = *(const float4*)p; qb1 = *(const float4*)(p + 4);
        }
        // ---- MMA kstep 1 ----
        {
            unsigned ah0[4], ah1[4];
            LDSM4(ah0, ab + 32);
            LDSM4(ah1, ab + 1312);
#pragma unroll
            for (int ntp = 0; ntp < 4; ntp++) {
                unsigned bh[4];
                LDSM4(bh, bb + ntp * 1280 + 32);
                MMA(&acc[(ntp * 2) * 4], ah0, bh[0], bh[1]);
                MMA(&acc[(ntp * 2 + 1) * 4], ah0, bh[2], bh[3]);
                MMA(&acc[(8 + ntp * 2) * 4], ah1, bh[0], bh[1]);
                MMA(&acc[(8 + ntp * 2 + 1) * 4], ah1, bh[2], bh[3]);
            }
        }
        // weight corners 2,3 -> sampA
        if (more) {
            sampA[0] = fmaf(mw.w, qb0.x, fmaf(mw.z, qa0.x, sampA[0]));
            sampA[1] = fmaf(mw.w, qb0.y, fmaf(mw.z, qa0.y, sampA[1]));
            sampA[2] = fmaf(mw.w, qb0.z, fmaf(mw.z, qa0.z, sampA[2]));
            sampA[3] = fmaf(mw.w, qb0.w, fmaf(mw.z, qa0.w, sampA[3]));
            sampA[4] = fmaf(mw.w, qb1.x, fmaf(mw.z, qa1.x, sampA[4]));
            sampA[5] = fmaf(mw.w, qb1.y, fmaf(mw.z, qa1.y, sampA[5]));
            sampA[6] = fmaf(mw.w, qb1.z, fmaf(mw.z, qa1.z, sampA[6]));
            sampA[7] = fmaf(mw.w, qb1.w, fmaf(mw.z, qa1.w, sampA[7]));
        }
        // no end-of-loop barrier (mid barrier of next iter orders reuse)
    }
    __syncthreads();

    // ---- epilogue: bias add, store, fused GN partial stats ----
    float pg[4] = {0.f, 0.f, 0.f, 0.f};
    float pq[4] = {0.f, 0.f, 0.f, 0.f};
    int pxb = p0 + wm * 32 + (lane >> 2);
#pragma unroll
    for (int mt = 0; mt < 2; mt++) {
#pragma unroll
        for (int nt = 0; nt < 8; nt++) {
            float* ap = &acc[(mt * 8 + nt) * 4];
            int o = wn * 64 + nt * 8 + (lane & 3) * 2;
            float bv0 = __ldg(bias + o), bv1 = __ldg(bias + o + 1);
            int pxm = pxb + mt * 16;
            size_t r0 = (((size_t)(b * 256 + o)) << 12) + pxm;
            size_t r1 = r0 + 4096;
            float v0 = ap[0] + bv0, v1 = ap[1] + bv1;
            float v2 = ap[2] + bv0, v3 = ap[3] + bv1;
            g_conv[r0] = v0;
            g_conv[r1] = v1;
            g_conv[r0 + 8] = v2;
            g_conv[r1 + 8] = v3;
            int j = nt >> 1;
            pg[j] += v0 + v1 + v2 + v3;
            pq[j] += v0 * v0 + v1 * v1 + v2 * v2 + v3 * v3;
        }
    }
#pragma unroll
    for (int j = 0; j < 4; j++) {
#pragma unroll
        for (int s = 16; s > 0; s >>= 1) {
            pg[j] += __shfl_down_sync(0xFFFFFFFFu, pg[j], s);
            pq[j] += __shfl_down_sync(0xFFFFFFFFu, pq[j], s);
        }
    }
    float* red = (float*)sm;   // 16 warps x 8 floats
    if (lane == 0) {
#pragma unroll
        for (int j = 0; j < 4; j++) {
            red[wid * 8 + j] = pg[j];
            red[wid * 8 + 4 + j] = pq[j];
        }
    }
    __syncthreads();
    if (tid < 32) {
        int group = tid >> 1, which = tid & 1;
        int wnb = group >> 2;
        float v = 0.f;
#pragma unroll
        for (int wmi = 0; wmi < 4; wmi++)
            v += red[(wnb * 4 + wmi) * 8 + (group & 3) + 4 * which];
        if (which == 0) g_psum[(b * 16 + group) * 32 + tile] = v;
        else            g_pssum[(b * 16 + group) * 32 + tile] = v;
    }
}

// ---------------------------------------------------------------------------
// GN stats finalize: 64 blocks x 32 threads
// ---------------------------------------------------------------------------
__global__ void k_statsF() {
    int bg = blockIdx.x, t = threadIdx.x;
    float s = g_psum[bg * 32 + t];
    float q = g_pssum[bg * 32 + t];
#pragma unroll
    for (int o = 16; o > 0; o >>= 1) {
        s += __shfl_down_sync(0xFFFFFFFFu, s, o);
        q += __shfl_down_sync(0xFFFFFFFFu, q, o);
    }
    if (t == 0) {
        float mu = s * (1.f / 65536.f);
        float var = q * (1.f / 65536.f) - mu * mu;
        g_mu[bg] = mu;
        g_rs[bg] = rsqrtf(var + 1e-5f);
    }
}

// ---------------------------------------------------------------------------
// Normalize + affine -> d_out.  2048 blocks x 256 thr x 2 float4.
// ---------------------------------------------------------------------------
__global__ void k_norm(const float* __restrict__ gamma,
                       const float* __restrict__ beta,
                       float* __restrict__ out) {
    int i = blockIdx.x * 512 + threadIdx.x;
#pragma unroll
    for (int t = 0; t < 2; t++, i += 256) {
        float4 v = ((const float4*)g_conv)[i];
        int bc = i >> 10;
        int c = bc & 255, b = bc >> 8;
        int bg = b * 16 + (c >> 4);
        float sc = g_rs[bg] * gamma[c];
        float sh = beta[c] - g_mu[bg] * sc;
        v.x = v.x * sc + sh;
        v.y = v.y * sc + sh;
        v.z = v.z * sc + sh;
        v.w = v.w * sc + sh;
        ((float4*)out)[i] = v;
    }
}

// ---------------------------------------------------------------------------
extern "C" void kernel_launch(void* const* d_in, const int* in_sizes, int n_in,
                              void* d_out, int out_size) {
    const float* x = nullptr;
    const float* w_off = nullptr;
    const float* b_off = nullptr;
    const float* weight = nullptr;
    const float* v256[3] = {nullptr, nullptr, nullptr};
    int n256 = 0;
    for (int i = 0; i < n_in; i++) {
        int s = in_sizes[i];
        const float* ptr = (const float*)d_in[i];
        if (s == 4194304) x = ptr;
        else if (s == 62208) w_off = ptr;
        else if (s == 27) b_off = ptr;
        else if (s == 589824) weight = ptr;
        else if (s == 256 && n256 < 3) v256[n256++] = ptr;
    }
    const float* bias  = v256[0];
    const float* gamma = v256[1];
    const float* beta  = v256[2];
    float* out = (float*)d_out;

    cudaFuncSetAttribute(k_mainTC, cudaFuncAttributeMaxDynamicSharedMemorySize,
                         SMEM_TOTAL);

    k_xT<<<4096, 256>>>(x);
    k_prepW<<<256, 256>>>(weight);
    k_offW<<<72, 256>>>(w_off);
    k_mainTC<<<128, 512, SMEM_TOTAL>>>(b_off, bias);
    k_statsF<<<64, 32>>>();
    k_norm<<<2048, 256>>>(gamma, beta, out);
}

// round 14
// speedup vs baseline: 2.1708x; 1.1394x over previous
#include <cuda_runtime.h>
#include <cuda_fp16.h>
#include <cstdint>

// ---------------------------------------------------------------------------
// DCNv2 + GroupNorm16.  B=4, Cin=Cout=256, H=W=64, K=3, s=1, p=1, g=16.
// Fused tensor-core kernel (M=128 tiles, 512 thr, grid 128), K-chunks of 64:
//  phase1 = offset conv HMMA (fp16 im2col A) + bilinear meta (idx + fp16x2
//  weights) in smem; phase2 = deformable-sampled HMMA GEMM with fp16 gathers
//  and fp16 bilinear combine (HMUL2/HFMA2, zero converts), B single fp16.
//  One barrier per 64-chunk. GN partial stats fused in epilogue.
// compute_103 baseline PTX only.
// ---------------------------------------------------------------------------

// ---- device-global scratch -------------------------------------------------
__device__ __half g_xH[4 * 4096 * 256];       // x NHWC fp16
__device__ __half g_wF16[72 * 256 * 32];      // main weight fp16 [ci32][o][k]
__device__ __half g_wOf[72 * 32 * 32];        // offset weight fp16 [ci32][o32][k]
__device__ float  g_conv[4 * 256 * 4096];     // conv out (pre-GN)
__device__ float  g_psum[64 * 32];            // per-(bg,tile) partial sums
__device__ float  g_pssum[64 * 32];
__device__ float  g_mu[64];
__device__ float  g_rs[64];

// ---- PTX helpers ----------------------------------------------------------
__device__ __forceinline__ unsigned smem_u32(const void* p) {
    unsigned a;
    asm("{ .reg .u64 t; cvta.to.shared.u64 t, %1; cvt.u32.u64 %0, t; }"
        : "=r"(a) : "l"(p));
    return a;
}
#define CP16(s, g) asm volatile("cp.async.cg.shared.global [%0], [%1], 16;" :: "r"(s), "l"(g) : "memory")
#define CP_COMMIT() asm volatile("cp.async.commit_group;" ::: "memory")
#define CP_WAIT0()  asm volatile("cp.async.wait_group 0;" ::: "memory")

#define LDSM4(r, addr)                                                        \
    asm volatile("ldmatrix.sync.aligned.m8n8.x4.shared.b16 {%0,%1,%2,%3}, [%4];" \
                 : "=r"((r)[0]), "=r"((r)[1]), "=r"((r)[2]), "=r"((r)[3])     \
                 : "r"(addr))

#define MMA(ap, a, b0, b1)                                                    \
    asm volatile("mma.sync.aligned.m16n8k16.row.col.f32.f16.f16.f32 "         \
                 "{%0,%1,%2,%3}, {%4,%5,%6,%7}, {%8,%9}, {%0,%1,%2,%3};"      \
                 : "+f"((ap)[0]), "+f"((ap)[1]), "+f"((ap)[2]), "+f"((ap)[3]) \
                 : "r"((a)[0]), "r"((a)[1]), "r"((a)[2]), "r"((a)[3]),        \
                   "r"(b0), "r"(b1))

#define U2H(u) (*reinterpret_cast<const __half2*>(&(u)))
#define H2U(h) (*reinterpret_cast<const unsigned*>(&(h)))

// ---------------------------------------------------------------------------
// x NCHW fp32 -> NHWC fp16
// ---------------------------------------------------------------------------
__global__ void k_xT(const float* __restrict__ x) {
    __shared__ float t[32][33];
    int bx = blockIdx.x;                    // 4096 = b(4) * cblk(8) * pxblk(128)
    int pxb = bx & 127, cb = (bx >> 7) & 7, b = bx >> 10;
    int tx = threadIdx.x & 31, ty = threadIdx.x >> 5;
#pragma unroll
    for (int i = 0; i < 4; i++) {
        int c = cb * 32 + ty + i * 8;
        t[ty + i * 8][tx] = x[(((size_t)(b * 256 + c)) << 12) + pxb * 32 + tx];
    }
    __syncthreads();
#pragma unroll
    for (int i = 0; i < 4; i++) {
        int px = pxb * 32 + ty + i * 8;
        g_xH[(((size_t)b << 12) + px) * 256 + cb * 32 + tx] =
            __float2half(t[tx][ty + i * 8]);
    }
}

// ---------------------------------------------------------------------------
// main weight [O][C][3][3] -> fp16 [ci32][o][k32]; ci32 = tap*8+cb, c=cb*32+k
// ---------------------------------------------------------------------------
__global__ void k_prepW(const float* __restrict__ w) {
    int o = blockIdx.x;
    for (int idx = threadIdx.x; idx < 2304; idx += 256) {
        int ci = idx >> 5, k = idx & 31;
        int tap = ci >> 3, c = ((ci & 7) << 5) + k;
        g_wF16[(size_t)ci * 8192 + o * 32 + k] =
            __float2half(w[o * 2304 + c * 9 + tap]);
    }
}

// ---------------------------------------------------------------------------
// offset weight [27][C][3][3] -> fp16 [ci32][o(32, >=27 zero)][k32]
// ---------------------------------------------------------------------------
__global__ void k_offW(const float* __restrict__ wof) {
    int ci = blockIdx.x;
    int tap = ci >> 3, cb = ci & 7;
    for (int i = threadIdx.x; i < 1024; i += 256) {
        int o = i >> 5, k = i & 31;
        int c = (cb << 5) + k;
        float v = (o < 27) ? wof[o * 2304 + c * 9 + tap] : 0.f;
        g_wOf[ci * 1024 + i] = __float2half(v);
    }
}

// ---------------------------------------------------------------------------
// Fused kernel. Grid 128 = (b, 32 px-tiles of 128). 512 threads.
// SMEM (dynamic, 147456 B), rows padded to 144B (conflict-free for ldmatrix):
//   SA[buf]: 128 rows x 144B = 18432 each -> [0, 36864)
//   SB[buf]: 256 rows x 144B = 36864 each -> [36864, 110592)
//     (phase1 uses first 32 rows of each SB buf; om scratch 128x32 f32
//      overlays SB(0) between phases)
//   META_I: idx[9][128][4] int        -> [110592, 129024)
//   META_W: wgt[9][128][4] fp16x2-dup -> [129024, 147456)
// ---------------------------------------------------------------------------
#define SA(buf)   ((buf) * 18432)
#define SB(buf)   (36864 + (buf) * 36864)
#define META_I    110592
#define META_W    129024
#define SMEM_TOTAL 147456

__global__ __launch_bounds__(512, 1) void k_mainTC(const float* __restrict__ bof,
                                                   const float* __restrict__ bias) {
    extern __shared__ char sm[];
    unsigned smb = smem_u32(sm);
    int tid = threadIdx.x, lane = tid & 31, wid = tid >> 5;
    int b = blockIdx.x >> 5;
    int tile = blockIdx.x & 31;
    int p0 = tile << 7;

    int px = tid >> 2, oct = tid & 3;     // A staging role (both phases)
    unsigned aoff = (unsigned)((lane & 15) * 144 + (lane >> 4) * 16);
    unsigned boff = (unsigned)((lane & 7) * 144 + ((lane >> 3) & 1) * 16 +
                               (lane >> 4) * 1152);
    unsigned ao = (unsigned)(px * 144 + oct * 32);
    const __half* xh = g_xH + ((size_t)b << 20);

    // =======================================================================
    // Phase 1: offset conv HMMA (fp16 im2col A), K-chunks of 64 (36 chunks).
    // 16 warps = (wm1 0..7) x (wn1 0..1), warp tile 16x16, 4 ksteps.
    // =======================================================================
    {
        int wm1 = wid & 7, wn1 = wid >> 3;
        float acc1[2][4];
#pragma unroll
        for (int i = 0; i < 2; i++)
#pragma unroll
            for (int j = 0; j < 4; j++) acc1[i][j] = 0.f;

        int gp = p0 + px, h = gp >> 6, w = gp & 63;
        uint4 qA0, qA1;
        auto loadA1 = [&](int ci) {
            int tap = ci >> 2, cb = ci & 3;
            int py = h + tap / 3 - 1, pxx = w + tap % 3 - 1;
            if (py >= 0 && py < 64 && pxx >= 0 && pxx < 64) {
                const __half* s = xh + (((size_t)(py * 64 + pxx)) << 8) +
                                  (cb << 6) + (oct << 4);
                qA0 = *(const uint4*)s;
                qA1 = *(const uint4*)(s + 8);
            } else {
                qA0 = make_uint4(0u, 0u, 0u, 0u);
                qA1 = make_uint4(0u, 0u, 0u, 0u);
            }
        };
        auto loadB1 = [&](int ci, int buf) {
            if (tid < 256) {
                int tap = ci >> 2, cb = ci & 3;
                int row = tid >> 3, q = tid & 7;
                const __half* src = g_wOf +
                    (size_t)(tap * 8 + cb * 2 + (q >> 2)) * 1024 + row * 32 +
                    (q & 3) * 8;
                CP16(smb + SB(buf) + row * 144 + q * 16, src);
            }
            CP_COMMIT();
        };

        loadA1(0);
        loadB1(0, 0);
#pragma unroll 1
        for (int ci = 0; ci < 36; ci++) {
            int buf = ci & 1;
            *(uint4*)(sm + SA(buf) + ao) = qA0;
            *(uint4*)(sm + SA(buf) + ao + 16) = qA1;
            CP_WAIT0();
            __syncthreads();
            if (ci < 35) { loadA1(ci + 1); loadB1(ci + 1, buf ^ 1); }
            unsigned aB = smb + (unsigned)(SA(buf) + wm1 * 2304) + aoff;
            unsigned bB = smb + (unsigned)(SB(buf) + wn1 * 2304) + boff;
#pragma unroll
            for (int ks = 0; ks < 4; ks++) {
                unsigned ah[4], bh[4];
                LDSM4(ah, aB + ks * 32);
                LDSM4(bh, bB + ks * 32);
                MMA(acc1[0], ah, bh[0], bh[1]);
                MMA(acc1[1], ah, bh[2], bh[3]);
            }
        }
        __syncthreads();
        // om scratch (128 x 32 f32) overlaying SB(0)
        float* som = (float*)(sm + SB(0));
        {
            int row = wm1 * 16 + (lane >> 2);
            int col = wn1 * 16 + (lane & 3) * 2;
#pragma unroll
            for (int nt = 0; nt < 2; nt++) {
                int c = col + nt * 8;
                som[row * 32 + c] = acc1[nt][0];
                som[row * 32 + c + 1] = acc1[nt][1];
                som[(row + 8) * 32 + c] = acc1[nt][2];
                som[(row + 8) * 32 + c + 1] = acc1[nt][3];
            }
        }
        __syncthreads();
        // bilinear meta -> smem META (idx int, weight*mask as fp16x2-dup)
        int* sIdx = (int*)(sm + META_I);
        unsigned* sWgtH = (unsigned*)(sm + META_W);
        for (int idx = tid; idx < 1152; idx += 512) {
            int pr = idx / 9, k = idx - pr * 9;
            float ay = som[pr * 32 + k] + __ldg(bof + k);
            float ax = som[pr * 32 + k + 9] + __ldg(bof + k + 9);
            float am = som[pr * 32 + k + 18] + __ldg(bof + k + 18);
            float m = 1.f / (1.f + __expf(-am));
            int gp2 = p0 + pr, hh = gp2 >> 6, ww = gp2 & 63;
            float py = (float)(hh + k / 3 - 1) + ay;
            float pxx = (float)(ww + (k - (k / 3) * 3) - 1) + ax;
            float y0f = floorf(py), x0f = floorf(pxx);
            float wy1 = py - y0f, wx1 = pxx - x0f;
            int y0 = (int)y0f, x0 = (int)x0f;
            int mo = (k * 128 + pr) * 4;
#pragma unroll
            for (int j = 0; j < 4; j++) {
                int dy = j >> 1, dx = j & 1;
                int yy = y0 + dy, xx = x0 + dx;
                float wv = (dy ? wy1 : 1.f - wy1) * (dx ? wx1 : 1.f - wx1);
                bool valid = (yy >= 0) && (yy < 64) && (xx >= 0) && (xx < 64);
                int yc = min(max(yy, 0), 63), xc = min(max(xx, 0), 63);
                sIdx[mo + j] = yc * 64 + xc;
                float wvm = valid ? wv * m : 0.f;
                unsigned hv = (unsigned)__half_as_ushort(__float2half(wvm));
                sWgtH[mo + j] = hv | (hv << 16);
            }
        }
        __syncthreads();
    }

    // =======================================================================
    // Phase 2: main deformable GEMM, K-chunks of 64 (36 chunks).
    // 16 warps = (wm 0..3) x (wn 0..3), warp tile 32x64, 4 ksteps.
    // fp16 gathers + fp16 bilinear combine (zero converts).
    // =======================================================================
    int wm = wid & 3, wn = wid >> 2;
    float acc[64];
#pragma unroll
    for (int i = 0; i < 64; i++) acc[i] = 0.f;

    int4 mi;
    uint4 mwh;                 // 4 fp16x2-dup corner weights
    __half2 sH[8];             // sampled 16 channels (fp16x2)
    uint4 r0, r1, r2, r3;      // two raw corners (16 fp16 each)
    const int* sIdx = (const int*)(sm + META_I);
    const unsigned* sWgtH = (const unsigned*)(sm + META_W);

    auto meta2 = [&](int tap) {
        mi = *(const int4*)(sIdx + (tap * 128 + px) * 4);
        mwh = *(const uint4*)(sWgtH + (tap * 128 + px) * 4);
    };
    auto loadB2 = [&](int ci, int buf) {
        int tap = ci >> 2, cb = ci & 3;
        int row = tid >> 1, seg = tid & 1;
        const __half* g = g_wF16 +
            (size_t)(tap * 8 + cb * 2 + seg) * 8192 + row * 32;
        unsigned s = smb + SB(buf) + row * 144 + seg * 64;
        CP16(s, g); CP16(s + 16, g + 8);
        CP16(s + 32, g + 16); CP16(s + 48, g + 24);
        CP_COMMIT();
    };
    auto issue01 = [&](int cb) {
        unsigned cbase = ((unsigned)cb << 6) + ((unsigned)oct << 4);
        const __half* g0 = xh + (((size_t)mi.x) << 8) + cbase;
        r0 = *(const uint4*)g0; r1 = *(const uint4*)(g0 + 8);
        const __half* g1 = xh + (((size_t)mi.y) << 8) + cbase;
        r2 = *(const uint4*)g1; r3 = *(const uint4*)(g1 + 8);
    };
    auto consume01 = [&]() {
        __half2 w0 = U2H(mwh.x), w1 = U2H(mwh.y);
        sH[0] = __hfma2(w1, U2H(r2.x), __hmul2(w0, U2H(r0.x)));
        sH[1] = __hfma2(w1, U2H(r2.y), __hmul2(w0, U2H(r0.y)));
        sH[2] = __hfma2(w1, U2H(r2.z), __hmul2(w0, U2H(r0.z)));
        sH[3] = __hfma2(w1, U2H(r2.w), __hmul2(w0, U2H(r0.w)));
        sH[4] = __hfma2(w1, U2H(r3.x), __hmul2(w0, U2H(r1.x)));
        sH[5] = __hfma2(w1, U2H(r3.y), __hmul2(w0, U2H(r1.y)));
        sH[6] = __hfma2(w1, U2H(r3.z), __hmul2(w0, U2H(r1.z)));
        sH[7] = __hfma2(w1, U2H(r3.w), __hmul2(w0, U2H(r1.w)));
    };
    auto issue23 = [&](int cb) {
        unsigned cbase = ((unsigned)cb << 6) + ((unsigned)oct << 4);
        const __half* g2 = xh + (((size_t)mi.z) << 8) + cbase;
        r0 = *(const uint4*)g2; r1 = *(const uint4*)(g2 + 8);
        const __half* g3 = xh + (((size_t)mi.w) << 8) + cbase;
        r2 = *(const uint4*)g3; r3 = *(const uint4*)(g3 + 8);
    };
    auto consume23 = [&]() {
        __half2 w2 = U2H(mwh.z), w3 = U2H(mwh.w);
        sH[0] = __hfma2(w3, U2H(r2.x), __hfma2(w2, U2H(r0.x), sH[0]));
        sH[1] = __hfma2(w3, U2H(r2.y), __hfma2(w2, U2H(r0.y), sH[1]));
        sH[2] = __hfma2(w3, U2H(r2.z), __hfma2(w2, U2H(r0.z), sH[2]));
        sH[3] = __hfma2(w3, U2H(r2.w), __hfma2(w2, U2H(r0.w), sH[3]));
        sH[4] = __hfma2(w3, U2H(r3.x), __hfma2(w2, U2H(r1.x), sH[4]));
        sH[5] = __hfma2(w3, U2H(r3.y), __hfma2(w2, U2H(r1.y), sH[5]));
        sH[6] = __hfma2(w3, U2H(r3.z), __hfma2(w2, U2H(r1.z), sH[6]));
        sH[7] = __hfma2(w3, U2H(r3.w), __hfma2(w2, U2H(r1.w), sH[7]));
    };
    auto kstep = [&](unsigned ab, unsigned bb, int ks) {
        unsigned ah0[4], ah1[4];
        LDSM4(ah0, ab + ks * 32);
        LDSM4(ah1, ab + ks * 32 + 2304);
#pragma unroll
        for (int ntp = 0; ntp < 4; ntp++) {
            unsigned bh[4];
            LDSM4(bh, bb + ntp * 2304 + ks * 32);
            MMA(&acc[(ntp * 2) * 4], ah0, bh[0], bh[1]);
            MMA(&acc[(ntp * 2 + 1) * 4], ah0, bh[2], bh[3]);
            MMA(&acc[(8 + ntp * 2) * 4], ah1, bh[0], bh[1]);
            MMA(&acc[(8 + ntp * 2 + 1) * 4], ah1, bh[2], bh[3]);
        }
    };

    // prologue: compute sH for chunk 0 (eager), issue B chunk 0
    meta2(0);
    issue01(0); consume01();
    issue23(0); consume23();
    loadB2(0, 0);

#pragma unroll 1
    for (int ci = 0; ci < 36; ci++) {
        int buf = ci & 1;
        {
            uint4 u0 = make_uint4(H2U(sH[0]), H2U(sH[1]), H2U(sH[2]), H2U(sH[3]));
            uint4 u1 = make_uint4(H2U(sH[4]), H2U(sH[5]), H2U(sH[6]), H2U(sH[7]));
            *(uint4*)(sm + SA(buf) + ao) = u0;
            *(uint4*)(sm + SA(buf) + ao + 16) = u1;
        }
        CP_WAIT0();
        __syncthreads();

        int cn = ci + 1;
        bool more = cn < 36;
        int cb2 = cn & 3;
        if (more) {
            if (cb2 == 0) meta2(cn >> 2);
            issue01(cb2);
            loadB2(cn, buf ^ 1);
        }
        unsigned ab = smb + (unsigned)(SA(buf) + wm * 4608) + aoff;
        unsigned bb = smb + (unsigned)(SB(buf) + wn * 9216) + boff;
        kstep(ab, bb, 0);
        kstep(ab, bb, 1);
        if (more) { consume01(); issue23(cb2); }
        kstep(ab, bb, 2);
        kstep(ab, bb, 3);
        if (more) consume23();
        // no end-of-loop barrier (next iter's mid barrier orders reuse)
    }
    __syncthreads();

    // ---- epilogue: bias add, store, fused GN partial stats ----
    float pg[4] = {0.f, 0.f, 0.f, 0.f};
    float pq[4] = {0.f, 0.f, 0.f, 0.f};
    int pxb = p0 + wm * 32 + (lane >> 2);
#pragma unroll
    for (int mt = 0; mt < 2; mt++) {
#pragma unroll
        for (int nt = 0; nt < 8; nt++) {
            float* ap = &acc[(mt * 8 + nt) * 4];
            int o = wn * 64 + nt * 8 + (lane & 3) * 2;
            float bv0 = __ldg(bias + o), bv1 = __ldg(bias + o + 1);
            int pxm = pxb + mt * 16;
            size_t r0a = (((size_t)(b * 256 + o)) << 12) + pxm;
            size_t r1a = r0a + 4096;
            float v0 = ap[0] + bv0, v1 = ap[1] + bv1;
            float v2 = ap[2] + bv0, v3 = ap[3] + bv1;
            g_conv[r0a] = v0;
            g_conv[r1a] = v1;
            g_conv[r0a + 8] = v2;
            g_conv[r1a + 8] = v3;
            int j = nt >> 1;
            pg[j] += v0 + v1 + v2 + v3;
            pq[j] += v0 * v0 + v1 * v1 + v2 * v2 + v3 * v3;
        }
    }
#pragma unroll
    for (int j = 0; j < 4; j++) {
#pragma unroll
        for (int s = 16; s > 0; s >>= 1) {
            pg[j] += __shfl_down_sync(0xFFFFFFFFu, pg[j], s);
            pq[j] += __shfl_down_sync(0xFFFFFFFFu, pq[j], s);
        }
    }
    float* red = (float*)sm;   // 16 warps x 8 floats
    if (lane == 0) {
#pragma unroll
        for (int j = 0; j < 4; j++) {
            red[wid * 8 + j] = pg[j];
            red[wid * 8 + 4 + j] = pq[j];
        }
    }
    __syncthreads();
    if (tid < 32) {
        int group = tid >> 1, which = tid & 1;
        int wnb = group >> 2;
        float v = 0.f;
#pragma unroll
        for (int wmi = 0; wmi < 4; wmi++)
            v += red[(wnb * 4 + wmi) * 8 + (group & 3) + 4 * which];
        if (which == 0) g_psum[(b * 16 + group) * 32 + tile] = v;
        else            g_pssum[(b * 16 + group) * 32 + tile] = v;
    }
}

// ---------------------------------------------------------------------------
// GN stats finalize: 64 blocks x 32 threads
// ---------------------------------------------------------------------------
__global__ void k_statsF() {
    int bg = blockIdx.x, t = threadIdx.x;
    float s = g_psum[bg * 32 + t];
    float q = g_pssum[bg * 32 + t];
#pragma unroll
    for (int o = 16; o > 0; o >>= 1) {
        s += __shfl_down_sync(0xFFFFFFFFu, s, o);
        q += __shfl_down_sync(0xFFFFFFFFu, q, o);
    }
    if (t == 0) {
        float mu = s * (1.f / 65536.f);
        float var = q * (1.f / 65536.f) - mu * mu;
        g_mu[bg] = mu;
        g_rs[bg] = rsqrtf(var + 1e-5f);
    }
}

// ---------------------------------------------------------------------------
// Normalize + affine -> d_out.  2048 blocks x 256 thr x 2 float4.
// ---------------------------------------------------------------------------
__global__ void k_norm(const float* __restrict__ gamma,
                       const float* __restrict__ beta,
                       float* __restrict__ out) {
    int i = blockIdx.x * 512 + threadIdx.x;
#pragma unroll
    for (int t = 0; t < 2; t++, i += 256) {
        float4 v = ((const float4*)g_conv)[i];
        int bc = i >> 10;
        int c = bc & 255, b = bc >> 8;
        int bg = b * 16 + (c >> 4);
        float sc = g_rs[bg] * gamma[c];
        float sh = beta[c] - g_mu[bg] * sc;
        v.x = v.x * sc + sh;
        v.y = v.y * sc + sh;
        v.z = v.z * sc + sh;
        v.w = v.w * sc + sh;
        ((float4*)out)[i] = v;
    }
}

// ---------------------------------------------------------------------------
extern "C" void kernel_launch(void* const* d_in, const int* in_sizes, int n_in,
                              void* d_out, int out_size) {
    const float* x = nullptr;
    const float* w_off = nullptr;
    const float* b_off = nullptr;
    const float* weight = nullptr;
    const float* v256[3] = {nullptr, nullptr, nullptr};
    int n256 = 0;
    for (int i = 0; i < n_in; i++) {
        int s = in_sizes[i];
        const float* ptr = (const float*)d_in[i];
        if (s == 4194304) x = ptr;
        else if (s == 62208) w_off = ptr;
        else if (s == 27) b_off = ptr;
        else if (s == 589824) weight = ptr;
        else if (s == 256 && n256 < 3) v256[n256++] = ptr;
    }
    const float* bias  = v256[0];
    const float* gamma = v256[1];
    const float* beta  = v256[2];
    float* out = (float*)d_out;

    cudaFuncSetAttribute(k_mainTC, cudaFuncAttributeMaxDynamicSharedMemorySize,
                         SMEM_TOTAL);

    k_xT<<<4096, 256>>>(x);
    k_prepW<<<256, 256>>>(weight);
    k_offW<<<72, 256>>>(w_off);
    k_mainTC<<<128, 512, SMEM_TOTAL>>>(b_off, bias);
    k_statsF<<<64, 32>>>();
    k_norm<<<2048, 256>>>(gamma, beta, out);
}